// round 1
// baseline (speedup 1.0000x reference)
#include <cuda_runtime.h>
#include <math.h>

// ---------------- problem constants ----------------
#define NB   8
#define DIM  192
#define ST   64
#define HWSZ 4096            // 64*64
#define TOK  (NB*HWSZ)       // 32768
#define HID  768
#define CHL  64              // scan chunk length
#define NCH  (HWSZ/CHL)      // 64 chunks per batch sequence

// ---------------- scratch (device globals; no allocation) ----------------
__device__ float g_xn1[TOK*DIM];     // LN1(x)  (token-major)
__device__ float g_xn2[TOK*DIM];     // ssm_ln(LN1(x))
__device__ float g_proj[TOK*256];    // [dt | B | C | xp] projections
__device__ float g_h[TOK*ST];        // local scan states
__device__ float g_yh[TOK*ST];       // C * h
__device__ float g_ssm[TOK*DIM];     // ssm branch output (token-major)
__device__ float g_xr[(size_t)TOK*DIM]; // residual (NCHW layout)
__device__ float g_xn3[TOK*DIM];     // LN2(xr) token-major
__device__ float g_hid[(size_t)TOK*HID]; // MLP hidden
__device__ float g_wcat[256*DIM];    // concat weights [dt;B;C;xp]
__device__ float g_bias256[256];
__device__ float g_Aneg[ST];         // -exp(A_log)
__device__ float g_P[NB*NCH*ST];
__device__ float g_hend[NB*NCH*ST];
__device__ float g_hin[NB*NCH*ST];

// ---------------- prep: weight concat + bias + A ----------------
__global__ void k_prep(const float* __restrict__ dt_w, const float* __restrict__ B_w,
                       const float* __restrict__ C_w,  const float* __restrict__ xp_w,
                       const float* __restrict__ dt_b, const float* __restrict__ xp_b,
                       const float* __restrict__ A_log)
{
    int i = blockIdx.x * blockDim.x + threadIdx.x;
    if (i < 256*DIM) {
        int n = i / DIM, k = i - n*DIM;
        float v;
        if      (n < 64)  v = dt_w[n*DIM + k];
        else if (n < 128) v = B_w[(n-64)*DIM + k];
        else if (n < 192) v = C_w[(n-128)*DIM + k];
        else              v = xp_w[(n-192)*DIM + k];
        g_wcat[i] = v;
    }
    if (i < 256) {
        float b = 0.f;
        if (i < 64)        b = dt_b[i];
        else if (i >= 192) b = xp_b[i-192];
        g_bias256[i] = b;
    }
    if (i < ST) g_Aneg[i] = -expf(A_log[i]);
}

// ---------------- block reduction helper (sum of two values) ----------------
__device__ __forceinline__ void red2(float& a, float& b, float* sa, float* sb)
{
    __syncthreads();  // protect reuse of smem across calls
    unsigned m = 0xffffffffu;
    #pragma unroll
    for (int o = 16; o > 0; o >>= 1) {
        a += __shfl_down_sync(m, a, o);
        b += __shfl_down_sync(m, b, o);
    }
    int w = threadIdx.x >> 5, l = threadIdx.x & 31;
    if (l == 0) { sa[w] = a; sb[w] = b; }
    __syncthreads();
    if (threadIdx.x == 0) {
        float ta = 0.f, tb = 0.f;
        int nw = blockDim.x >> 5;
        for (int i = 0; i < nw; i++) { ta += sa[i]; tb += sb[i]; }
        sa[0] = ta; sb[0] = tb;
    }
    __syncthreads();
    a = sa[0]; b = sb[0];
}

// ---------------- LayerNorm kernels ----------------
// MODE 0: x (NCHW) -> g_xn1 (LN1), g_xn2 (ssm_ln(LN1))
// MODE 1: g_xr (NCHW) -> g_xn3 (LN2)
template<int MODE>
__global__ void k_ln(const float* __restrict__ xin,
                     const float* __restrict__ g1, const float* __restrict__ b1,
                     const float* __restrict__ g2, const float* __restrict__ b2)
{
    __shared__ float sa[8], sb[8];
    int tok = blockIdx.x;
    int c = threadIdx.x;
    int b = tok >> 12, hw = tok & (HWSZ-1);
    const float* src = (MODE == 0) ? xin : g_xr;
    float v = src[((size_t)(b*DIM + c))*HWSZ + hw];

    float s = v, s2 = v*v;
    red2(s, s2, sa, sb);
    float mean = s * (1.f/DIM);
    float var  = s2 * (1.f/DIM) - mean*mean;
    float y = (v - mean) * rsqrtf(var + 1e-5f) * g1[c] + b1[c];

    if (MODE == 0) {
        g_xn1[(size_t)tok*DIM + c] = y;
        float t = y, t2 = y*y;
        red2(t, t2, sa, sb);
        float m2 = t * (1.f/DIM);
        float v2 = t2 * (1.f/DIM) - m2*m2;
        float y2 = (y - m2) * rsqrtf(v2 + 1e-5f) * g2[c] + b2[c];
        g_xn2[(size_t)tok*DIM + c] = y2;
    } else {
        g_xn3[(size_t)tok*DIM + c] = y;
    }
}

// ---------------- SSM elementwise helpers ----------------
__device__ __forceinline__ void ssm_elems(float dt, float Bv, float xv, float An,
                                          float& Av, float& BX)
{
    // softplus (stable) * 0.01 + 1e-4
    float sp = fmaxf(dt, 0.f) + log1pf(expf(-fabsf(dt)));
    float delta = sp * 0.01f + 1e-4f;
    float dA = fminf(fmaxf(delta * An, -10.f), -1e-4f);
    Av = fminf(fmaxf(expf(dA), 0.001f), 0.999f);
    BX = delta * Bv * xv;
}

// ---------------- scan pass 1: local chunk scans ----------------
__global__ void k_scan1()
{
    int s = threadIdx.x;              // state 0..63
    int bidx = blockIdx.x;            // NB*NCH
    int b = bidx / NCH, ch = bidx - b*NCH;
    float An = g_Aneg[s];
    float h = 0.f, P = 1.f;
    int tok0 = b*HWSZ + ch*CHL;
    for (int t = 0; t < CHL; t++) {
        const float* p = g_proj + (size_t)(tok0 + t)*256;
        float dt = p[s], Bv = p[64+s], xv = p[192+s];
        float Av, BX;
        ssm_elems(dt, Bv, xv, An, Av, BX);
        bool first = (ch == 0) && (t == 0);     // global t==0: h = BX (no A factor)
        h = first ? BX : Av*(h + BX);
        P *= Av;
        g_h[(size_t)(tok0 + t)*ST + s] = h;
    }
    g_P[bidx*ST + s] = P;
    g_hend[bidx*ST + s] = h;
}

// ---------------- scan pass 2: chunk carry prefix ----------------
__global__ void k_scan2()
{
    int s = threadIdx.x;
    int b = blockIdx.x;
    float hin = 0.f;
    for (int ch = 0; ch < NCH; ch++) {
        int i = (b*NCH + ch)*ST + s;
        g_hin[i] = hin;
        hin = g_P[i]*hin + g_hend[i];
    }
}

// ---------------- scan pass 3: fix-up + y = C*h ----------------
__global__ void k_scan3()
{
    int s = threadIdx.x;
    int bidx = blockIdx.x;
    int b = bidx / NCH, ch = bidx - b*NCH;
    float hin = g_hin[bidx*ST + s];
    float An = g_Aneg[s];
    float P = 1.f;
    int tok0 = b*HWSZ + ch*CHL;
    for (int t = 0; t < CHL; t++) {
        const float* p = g_proj + (size_t)(tok0 + t)*256;
        float dt = p[s], Bv = p[64+s], xv = p[192+s];
        float Av, BX;
        ssm_elems(dt, Bv, xv, An, Av, BX);
        (void)BX;
        P *= Av;
        float hf = g_h[(size_t)(tok0 + t)*ST + s] + P*hin;
        float Cv = p[128 + s];
        g_yh[(size_t)(tok0 + t)*ST + s] = Cv * hf;
    }
}

// ---------------- depthwise conv + BN + residual combine (NCHW) ----------------
__global__ void k_combine(const float* __restrict__ x, const float* __restrict__ dw,
                          const float* __restrict__ bn_g, const float* __restrict__ bn_b,
                          const float* __restrict__ bn_rm, const float* __restrict__ bn_rv,
                          const float* __restrict__ aL, const float* __restrict__ aS)
{
    int w = threadIdx.x;             // 0..63
    int h = blockIdx.x;              // 0..63
    int c = blockIdx.y;              // 0..191
    int b = blockIdx.z;              // 0..7
    const float* xb = x + ((size_t)(b*DIM + c))*HWSZ;
    const float* wk = dw + c*9;
    float acc = 0.f;
    #pragma unroll
    for (int kh = 0; kh < 3; kh++) {
        int hh = h + kh - 1;
        if (hh < 0 || hh >= 64) continue;
        #pragma unroll
        for (int kw = 0; kw < 3; kw++) {
            int ww = w + kw - 1;
            if (ww < 0 || ww >= 64) continue;
            acc += xb[hh*64 + ww] * wk[kh*3 + kw];
        }
    }
    float scale = bn_g[c] * rsqrtf(bn_rv[c] + 1e-5f);
    float local = (acc - bn_rm[c]) * scale + bn_b[c];
    int tok = b*HWSZ + h*64 + w;
    float xr = xb[h*64 + w] + aL[0]*local + aS[0]*g_ssm[(size_t)tok*DIM + c];
    g_xr[((size_t)(b*DIM + c))*HWSZ + h*64 + w] = xr;
}

// ---------------- fp32 tiled GEMM: C[M,N] = A[M,K] @ Bw[N,K]^T ----------------
// EPI 0: A=g_xn2,  B=g_wcat, bias=g_bias256 -> g_proj
// EPI 1: A=g_yh,   B=out_w,  bias=out_b, + clip(D)*g_xn1 -> g_ssm
// EPI 2: A=g_xn3,  B=mlp_w1, bias=mlp_b1, gelu -> g_hid
// EPI 3: A=g_hid,  B=mlp_w2, bias=mlp_b2, out = g_xr + alpha*v -> d_out (NCHW)
template<int EPI, int N, int K>
__global__ void __launch_bounds__(256) k_gemm(const float* __restrict__ Bw,
                                              const float* __restrict__ bias,
                                              float* __restrict__ Cout,
                                              const float* __restrict__ Dp,
                                              const float* __restrict__ alpha)
{
    __shared__ float As[16][64];
    __shared__ float Bs[16][64];
    const float* A = (EPI == 0) ? g_xn2 : (EPI == 1) ? g_yh : (EPI == 2) ? g_xn3 : g_hid;
    const float* Bp = (EPI == 0) ? g_wcat : Bw;
    const float* bp = (EPI == 0) ? g_bias256 : bias;

    int tid = threadIdx.x;
    int tx = tid & 15, ty = tid >> 4;
    int row0 = blockIdx.y * 64, col0 = blockIdx.x * 64;
    int lm = tid >> 2;
    int lk = (tid & 3) * 4;
    const float* Ag = A + (size_t)(row0 + lm)*K + lk;
    const float* Bg = Bp + (size_t)(col0 + lm)*K + lk;

    float acc[4][4];
    #pragma unroll
    for (int i = 0; i < 4; i++)
        #pragma unroll
        for (int j = 0; j < 4; j++) acc[i][j] = 0.f;

    for (int k0 = 0; k0 < K; k0 += 16) {
        float4 av = *reinterpret_cast<const float4*>(Ag + k0);
        float4 bv = *reinterpret_cast<const float4*>(Bg + k0);
        As[lk+0][lm] = av.x; As[lk+1][lm] = av.y; As[lk+2][lm] = av.z; As[lk+3][lm] = av.w;
        Bs[lk+0][lm] = bv.x; Bs[lk+1][lm] = bv.y; Bs[lk+2][lm] = bv.z; Bs[lk+3][lm] = bv.w;
        __syncthreads();
        #pragma unroll
        for (int kk = 0; kk < 16; kk++) {
            float a[4], bb[4];
            #pragma unroll
            for (int i = 0; i < 4; i++) a[i]  = As[kk][ty*4 + i];
            #pragma unroll
            for (int j = 0; j < 4; j++) bb[j] = Bs[kk][tx*4 + j];
            #pragma unroll
            for (int i = 0; i < 4; i++)
                #pragma unroll
                for (int j = 0; j < 4; j++)
                    acc[i][j] = fmaf(a[i], bb[j], acc[i][j]);
        }
        __syncthreads();
    }

    float aM = (EPI == 3) ? alpha[0] : 0.f;
    #pragma unroll
    for (int i = 0; i < 4; i++) {
        int m = row0 + ty*4 + i;
        #pragma unroll
        for (int j = 0; j < 4; j++) {
            int n = col0 + tx*4 + j;
            float v = acc[i][j] + bp[n];
            if (EPI == 1) {
                float d = fminf(fmaxf(Dp[n], -2.f), 2.f);
                v += d * g_xn1[(size_t)m*DIM + n];
                g_ssm[(size_t)m*N + n] = v;
            } else if (EPI == 2) {
                v = 0.5f * v * (1.f + erff(v * 0.7071067811865476f));
                g_hid[(size_t)m*N + n] = v;
            } else if (EPI == 3) {
                int b = m >> 12, hw = m & (HWSZ-1);
                size_t idx = ((size_t)(b*DIM + n))*HWSZ + hw;
                Cout[idx] = g_xr[idx] + aM * v;
            } else {
                g_proj[(size_t)m*N + n] = v;
            }
        }
    }
}

// ---------------- launch ----------------
extern "C" void kernel_launch(void* const* d_in, const int* in_sizes, int n_in,
                              void* d_out, int out_size)
{
    const float* x        = (const float*)d_in[0];
    const float* ln1_g    = (const float*)d_in[1];
    const float* ln1_b    = (const float*)d_in[2];
    const float* ln2_g    = (const float*)d_in[3];
    const float* ln2_b    = (const float*)d_in[4];
    const float* dw_w     = (const float*)d_in[5];
    const float* bn_g     = (const float*)d_in[6];
    const float* bn_b     = (const float*)d_in[7];
    const float* bn_rm    = (const float*)d_in[8];
    const float* bn_rv    = (const float*)d_in[9];
    const float* ssm_ln_g = (const float*)d_in[10];
    const float* ssm_ln_b = (const float*)d_in[11];
    const float* xp_w     = (const float*)d_in[12];
    const float* xp_b     = (const float*)d_in[13];
    const float* dt_w     = (const float*)d_in[14];
    const float* dt_b     = (const float*)d_in[15];
    const float* A_log    = (const float*)d_in[16];
    const float* B_w      = (const float*)d_in[17];
    const float* C_w      = (const float*)d_in[18];
    const float* D_param  = (const float*)d_in[19];
    const float* out_w    = (const float*)d_in[20];
    const float* out_b    = (const float*)d_in[21];
    const float* mlp_w1   = (const float*)d_in[22];
    const float* mlp_b1   = (const float*)d_in[23];
    const float* mlp_w2   = (const float*)d_in[24];
    const float* mlp_b2   = (const float*)d_in[25];
    const float* aL       = (const float*)d_in[26];
    const float* aS       = (const float*)d_in[27];
    const float* aM       = (const float*)d_in[28];
    float* out = (float*)d_out;

    // 1. prep concat weights / bias / A
    k_prep<<<192, 256>>>(dt_w, B_w, C_w, xp_w, dt_b, xp_b, A_log);

    // 2. LN1 + ssm_ln
    k_ln<0><<<TOK, DIM>>>(x, ln1_g, ln1_b, ssm_ln_g, ssm_ln_b);

    // 3. projections: [TOK,192] x [256,192]^T -> g_proj
    k_gemm<0, 256, 192><<<dim3(256/64, TOK/64), 256>>>(nullptr, nullptr, nullptr, nullptr, nullptr);

    // 4. chunked scan
    k_scan1<<<NB*NCH, ST>>>();
    k_scan2<<<NB, ST>>>();
    k_scan3<<<NB*NCH, ST>>>();

    // 5. out projection + D*xn1 -> g_ssm
    k_gemm<1, 192, 64><<<dim3(192/64, TOK/64), 256>>>(out_w, out_b, nullptr, D_param, nullptr);

    // 6. depthwise conv + BN + residual combine -> g_xr (NCHW)
    k_combine<<<dim3(64, DIM, NB), 64>>>(x, dw_w, bn_g, bn_b, bn_rm, bn_rv, aL, aS);

    // 7. LN2 -> g_xn3
    k_ln<1><<<TOK, DIM>>>(nullptr, ln2_g, ln2_b, nullptr, nullptr);

    // 8. MLP fc1 + gelu -> g_hid
    k_gemm<2, HID, 192><<<dim3(HID/64, TOK/64), 256>>>(mlp_w1, mlp_b1, nullptr, nullptr, nullptr);

    // 9. MLP fc2 + final residual -> d_out (NCHW)
    k_gemm<3, 192, HID><<<dim3(192/64, TOK/64), 256>>>(mlp_w2, mlp_b2, out, nullptr, aM);
}

// round 2
// speedup vs baseline: 1.8214x; 1.8214x over previous
#include <cuda_runtime.h>
#include <math.h>
#include <stdint.h>

// ---------------- problem constants ----------------
#define NB   8
#define DIM  192
#define ST   64
#define HWSZ 4096            // 64*64
#define TOK  (NB*HWSZ)       // 32768
#define HID  768
#define CHL  64              // scan chunk length
#define NCH  (HWSZ/CHL)      // 64 chunks per batch sequence

// ---------------- scratch (device globals; no allocation) ----------------
__device__ float g_xn1[TOK*DIM];     // LN1(x)  fp32 (used in EPI1 epilogue)
__device__ float g_xn2[TOK*DIM];     // ssm_ln(LN1(x)), tf32-rounded
__device__ float g_proj[TOK*256];    // [dt | B | C | xp] projections (fp32)
__device__ float g_h[TOK*ST];        // local scan states
__device__ float g_yh[TOK*ST];       // C * h, tf32-rounded
__device__ float g_ssm[TOK*DIM];     // ssm branch output (token-major, fp32)
__device__ float g_xr[(size_t)TOK*DIM]; // residual (NCHW layout, fp32)
__device__ float g_xn3[TOK*DIM];     // LN2(xr), tf32-rounded
__device__ float g_hid[(size_t)TOK*HID]; // MLP hidden, tf32-rounded
__device__ float g_wcat[256*DIM];    // concat weights [dt;B;C;xp], tf32
__device__ float g_wout[DIM*ST];     // out_w tf32
__device__ float g_w1[HID*DIM];      // mlp_w1 tf32
__device__ float g_w2[DIM*HID];      // mlp_w2 tf32
__device__ float g_bias256[256];
__device__ float g_Aneg[ST];         // -exp(A_log)
__device__ float g_P[NB*NCH*ST];
__device__ float g_hend[NB*NCH*ST];
__device__ float g_hin[NB*NCH*ST];

// ---------------- tf32 round helper ----------------
__device__ __forceinline__ float tf32r(float x)
{
    uint32_t u;
    asm("cvt.rna.tf32.f32 %0, %1;" : "=r"(u) : "f"(x));
    return __uint_as_float(u);
}

// ---------------- prep: weight concat + tf32 conversion + bias + A ----------------
__global__ void k_prep(const float* __restrict__ dt_w, const float* __restrict__ B_w,
                       const float* __restrict__ C_w,  const float* __restrict__ xp_w,
                       const float* __restrict__ dt_b, const float* __restrict__ xp_b,
                       const float* __restrict__ A_log, const float* __restrict__ out_w,
                       const float* __restrict__ mlp_w1, const float* __restrict__ mlp_w2)
{
    int i = blockIdx.x * blockDim.x + threadIdx.x;
    if (i < 256*DIM) {
        int n = i / DIM, k = i - n*DIM;
        float v;
        if      (n < 64)  v = dt_w[n*DIM + k];
        else if (n < 128) v = B_w[(n-64)*DIM + k];
        else if (n < 192) v = C_w[(n-128)*DIM + k];
        else              v = xp_w[(n-192)*DIM + k];
        g_wcat[i] = tf32r(v);
    }
    if (i < DIM*ST)  g_wout[i] = tf32r(out_w[i]);
    if (i < HID*DIM) { g_w1[i] = tf32r(mlp_w1[i]); g_w2[i] = tf32r(mlp_w2[i]); }
    if (i < 256) {
        float b = 0.f;
        if (i < 64)        b = dt_b[i];
        else if (i >= 192) b = xp_b[i-192];
        g_bias256[i] = b;
    }
    if (i < ST) g_Aneg[i] = -expf(A_log[i]);
}

// ---------------- block reduction helper (sum of two values) ----------------
__device__ __forceinline__ void red2(float& a, float& b, float* sa, float* sb)
{
    __syncthreads();
    unsigned m = 0xffffffffu;
    #pragma unroll
    for (int o = 16; o > 0; o >>= 1) {
        a += __shfl_down_sync(m, a, o);
        b += __shfl_down_sync(m, b, o);
    }
    int w = threadIdx.x >> 5, l = threadIdx.x & 31;
    if (l == 0) { sa[w] = a; sb[w] = b; }
    __syncthreads();
    if (threadIdx.x == 0) {
        float ta = 0.f, tb = 0.f;
        int nw = blockDim.x >> 5;
        for (int i = 0; i < nw; i++) { ta += sa[i]; tb += sb[i]; }
        sa[0] = ta; sb[0] = tb;
    }
    __syncthreads();
    a = sa[0]; b = sb[0];
}

// ---------------- LayerNorm kernels ----------------
// MODE 0: x (NCHW) -> g_xn1 (fp32), g_xn2 (tf32)
// MODE 1: g_xr (NCHW) -> g_xn3 (tf32)
template<int MODE>
__global__ void k_ln(const float* __restrict__ xin,
                     const float* __restrict__ g1, const float* __restrict__ b1,
                     const float* __restrict__ g2, const float* __restrict__ b2)
{
    __shared__ float sa[8], sb[8];
    int tok = blockIdx.x;
    int c = threadIdx.x;
    int b = tok >> 12, hw = tok & (HWSZ-1);
    const float* src = (MODE == 0) ? xin : g_xr;
    float v = src[((size_t)(b*DIM + c))*HWSZ + hw];

    float s = v, s2 = v*v;
    red2(s, s2, sa, sb);
    float mean = s * (1.f/DIM);
    float var  = s2 * (1.f/DIM) - mean*mean;
    float y = (v - mean) * rsqrtf(var + 1e-5f) * g1[c] + b1[c];

    if (MODE == 0) {
        g_xn1[(size_t)tok*DIM + c] = y;
        float t = y, t2 = y*y;
        red2(t, t2, sa, sb);
        float m2 = t * (1.f/DIM);
        float v2 = t2 * (1.f/DIM) - m2*m2;
        float y2 = (y - m2) * rsqrtf(v2 + 1e-5f) * g2[c] + b2[c];
        g_xn2[(size_t)tok*DIM + c] = tf32r(y2);
    } else {
        g_xn3[(size_t)tok*DIM + c] = tf32r(y);
    }
}

// ---------------- SSM elementwise helpers ----------------
__device__ __forceinline__ void ssm_elems(float dt, float Bv, float xv, float An,
                                          float& Av, float& BX)
{
    float sp = fmaxf(dt, 0.f) + log1pf(expf(-fabsf(dt)));
    float delta = sp * 0.01f + 1e-4f;
    float dA = fminf(fmaxf(delta * An, -10.f), -1e-4f);
    Av = fminf(fmaxf(expf(dA), 0.001f), 0.999f);
    BX = delta * Bv * xv;
}

// ---------------- scan pass 1: local chunk scans ----------------
__global__ void k_scan1()
{
    int s = threadIdx.x;
    int bidx = blockIdx.x;
    int b = bidx / NCH, ch = bidx - b*NCH;
    float An = g_Aneg[s];
    float h = 0.f, P = 1.f;
    int tok0 = b*HWSZ + ch*CHL;
    for (int t = 0; t < CHL; t++) {
        const float* p = g_proj + (size_t)(tok0 + t)*256;
        float dt = p[s], Bv = p[64+s], xv = p[192+s];
        float Av, BX;
        ssm_elems(dt, Bv, xv, An, Av, BX);
        bool first = (ch == 0) && (t == 0);
        h = first ? BX : Av*(h + BX);
        P *= Av;
        g_h[(size_t)(tok0 + t)*ST + s] = h;
    }
    g_P[bidx*ST + s] = P;
    g_hend[bidx*ST + s] = h;
}

// ---------------- scan pass 2: chunk carry prefix ----------------
__global__ void k_scan2()
{
    int s = threadIdx.x;
    int b = blockIdx.x;
    float hin = 0.f;
    for (int ch = 0; ch < NCH; ch++) {
        int i = (b*NCH + ch)*ST + s;
        g_hin[i] = hin;
        hin = g_P[i]*hin + g_hend[i];
    }
}

// ---------------- scan pass 3: fix-up + y = C*h (tf32) ----------------
__global__ void k_scan3()
{
    int s = threadIdx.x;
    int bidx = blockIdx.x;
    int b = bidx / NCH, ch = bidx - b*NCH;
    float hin = g_hin[bidx*ST + s];
    float An = g_Aneg[s];
    float P = 1.f;
    int tok0 = b*HWSZ + ch*CHL;
    for (int t = 0; t < CHL; t++) {
        const float* p = g_proj + (size_t)(tok0 + t)*256;
        float dt = p[s], Bv = p[64+s], xv = p[192+s];
        float Av, BX;
        ssm_elems(dt, Bv, xv, An, Av, BX);
        (void)BX;
        P *= Av;
        float hf = g_h[(size_t)(tok0 + t)*ST + s] + P*hin;
        float Cv = p[128 + s];
        g_yh[(size_t)(tok0 + t)*ST + s] = tf32r(Cv * hf);
    }
}

// ---------------- depthwise conv + BN + residual combine (NCHW) ----------------
__global__ void k_combine(const float* __restrict__ x, const float* __restrict__ dw,
                          const float* __restrict__ bn_g, const float* __restrict__ bn_b,
                          const float* __restrict__ bn_rm, const float* __restrict__ bn_rv,
                          const float* __restrict__ aL, const float* __restrict__ aS)
{
    int w = threadIdx.x;
    int h = blockIdx.x;
    int c = blockIdx.y;
    int b = blockIdx.z;
    const float* xb = x + ((size_t)(b*DIM + c))*HWSZ;
    const float* wk = dw + c*9;
    float acc = 0.f;
    #pragma unroll
    for (int kh = 0; kh < 3; kh++) {
        int hh = h + kh - 1;
        if (hh < 0 || hh >= 64) continue;
        #pragma unroll
        for (int kw = 0; kw < 3; kw++) {
            int ww = w + kw - 1;
            if (ww < 0 || ww >= 64) continue;
            acc += xb[hh*64 + ww] * wk[kh*3 + kw];
        }
    }
    float scale = bn_g[c] * rsqrtf(bn_rv[c] + 1e-5f);
    float local = (acc - bn_rm[c]) * scale + bn_b[c];
    int tok = b*HWSZ + h*64 + w;
    float xr = xb[h*64 + w] + aL[0]*local + aS[0]*g_ssm[(size_t)tok*DIM + c];
    g_xr[((size_t)(b*DIM + c))*HWSZ + h*64 + w] = xr;
}

// ---------------- tf32 mma helper ----------------
__device__ __forceinline__ void mma_tf32(float* c, const uint32_t* a, const uint32_t* b)
{
    asm volatile(
        "mma.sync.aligned.m16n8k8.row.col.f32.tf32.tf32.f32 "
        "{%0,%1,%2,%3}, {%4,%5,%6,%7}, {%8,%9}, {%0,%1,%2,%3};"
        : "+f"(c[0]), "+f"(c[1]), "+f"(c[2]), "+f"(c[3])
        : "r"(a[0]), "r"(a[1]), "r"(a[2]), "r"(a[3]), "r"(b[0]), "r"(b[1]));
}

// ---------------- TF32 tensor-core GEMM: C[M,N] = A[M,K] @ Bw[N,K]^T ----------------
// Block: 128 threads (4 warps), BM=128, BN=64, BK=32. Warp tile 32x64.
// EPI 0: A=g_xn2, B=g_wcat, bias=g_bias256 -> g_proj (fp32)
// EPI 1: A=g_yh,  B=g_wout, bias=out_b, + clip(D)*g_xn1 -> g_ssm (fp32)
// EPI 2: A=g_xn3, B=g_w1,   bias=mlp_b1, gelu -> g_hid (tf32)
// EPI 3: A=g_hid, B=g_w2,   bias=mlp_b2, out = g_xr + alpha*v -> d_out (NCHW)
template<int EPI, int N, int K>
__global__ void __launch_bounds__(128) k_mma(const float* __restrict__ bias,
                                             float* __restrict__ Cout,
                                             const float* __restrict__ Dp,
                                             const float* __restrict__ alpha)
{
    __shared__ uint32_t As[128][36];
    __shared__ uint32_t Bs[64][36];
    const float* A  = (EPI == 0) ? g_xn2 : (EPI == 1) ? g_yh : (EPI == 2) ? g_xn3 : g_hid;
    const float* Bp = (EPI == 0) ? g_wcat : (EPI == 1) ? g_wout : (EPI == 2) ? g_w1 : g_w2;
    const float* bp = (EPI == 0) ? g_bias256 : bias;

    int tid = threadIdx.x;
    int warp = tid >> 5, lane = tid & 31;
    int g = lane >> 2, t4 = lane & 3;
    int row0 = blockIdx.y * 128, col0 = blockIdx.x * 64;
    int m0 = warp * 32;

    float acc[2][8][4];
    #pragma unroll
    for (int mi = 0; mi < 2; mi++)
        #pragma unroll
        for (int ni = 0; ni < 8; ni++)
            #pragma unroll
            for (int e = 0; e < 4; e++) acc[mi][ni][e] = 0.f;

    for (int k0 = 0; k0 < K; k0 += 32) {
        // load A tile: 128x32 floats = 1024 float4, 8 per thread
        #pragma unroll
        for (int i = 0; i < 8; i++) {
            int f = tid + 128*i;
            int m = f >> 3, kq = f & 7;
            const float4 v = *reinterpret_cast<const float4*>(A + (size_t)(row0 + m)*K + k0 + kq*4);
            uint4 u = make_uint4(__float_as_uint(v.x), __float_as_uint(v.y),
                                 __float_as_uint(v.z), __float_as_uint(v.w));
            *reinterpret_cast<uint4*>(&As[m][kq*4]) = u;
        }
        // load B tile: 64x32 floats = 512 float4, 4 per thread
        #pragma unroll
        for (int i = 0; i < 4; i++) {
            int f = tid + 128*i;
            int n = f >> 3, kq = f & 7;
            const float4 v = *reinterpret_cast<const float4*>(Bp + (size_t)(col0 + n)*K + k0 + kq*4);
            uint4 u = make_uint4(__float_as_uint(v.x), __float_as_uint(v.y),
                                 __float_as_uint(v.z), __float_as_uint(v.w));
            *reinterpret_cast<uint4*>(&Bs[n][kq*4]) = u;
        }
        __syncthreads();

        #pragma unroll
        for (int k8 = 0; k8 < 4; k8++) {
            int kb = k8 * 8;
            uint32_t a[2][4], b[8][2];
            #pragma unroll
            for (int mi = 0; mi < 2; mi++) {
                int r = m0 + mi*16 + g;
                a[mi][0] = As[r][kb + t4];
                a[mi][1] = As[r + 8][kb + t4];
                a[mi][2] = As[r][kb + t4 + 4];
                a[mi][3] = As[r + 8][kb + t4 + 4];
            }
            #pragma unroll
            for (int ni = 0; ni < 8; ni++) {
                int c = ni*8 + g;
                b[ni][0] = Bs[c][kb + t4];
                b[ni][1] = Bs[c][kb + t4 + 4];
            }
            #pragma unroll
            for (int mi = 0; mi < 2; mi++)
                #pragma unroll
                for (int ni = 0; ni < 8; ni++)
                    mma_tf32(acc[mi][ni], a[mi], b[ni]);
        }
        __syncthreads();
    }

    // epilogue
    float aM = (EPI == 3) ? alpha[0] : 0.f;
    #pragma unroll
    for (int mi = 0; mi < 2; mi++) {
        #pragma unroll
        for (int ni = 0; ni < 8; ni++) {
            #pragma unroll
            for (int e = 0; e < 4; e++) {
                int m = row0 + m0 + mi*16 + g + ((e >> 1) << 3);
                int n = col0 + ni*8 + t4*2 + (e & 1);
                float v = acc[mi][ni][e] + bp[n];
                if (EPI == 0) {
                    g_proj[(size_t)m*N + n] = v;
                } else if (EPI == 1) {
                    float d = fminf(fmaxf(Dp[n], -2.f), 2.f);
                    v += d * g_xn1[(size_t)m*DIM + n];
                    g_ssm[(size_t)m*N + n] = v;
                } else if (EPI == 2) {
                    v = 0.5f * v * (1.f + erff(v * 0.7071067811865476f));
                    g_hid[(size_t)m*N + n] = tf32r(v);
                } else {
                    int b = m >> 12, hw = m & (HWSZ-1);
                    size_t idx = ((size_t)(b*DIM + n))*HWSZ + hw;
                    Cout[idx] = g_xr[idx] + aM * v;
                }
            }
        }
    }
}

// ---------------- launch ----------------
extern "C" void kernel_launch(void* const* d_in, const int* in_sizes, int n_in,
                              void* d_out, int out_size)
{
    const float* x        = (const float*)d_in[0];
    const float* ln1_g    = (const float*)d_in[1];
    const float* ln1_b    = (const float*)d_in[2];
    const float* ln2_g    = (const float*)d_in[3];
    const float* ln2_b    = (const float*)d_in[4];
    const float* dw_w     = (const float*)d_in[5];
    const float* bn_g     = (const float*)d_in[6];
    const float* bn_b     = (const float*)d_in[7];
    const float* bn_rm    = (const float*)d_in[8];
    const float* bn_rv    = (const float*)d_in[9];
    const float* ssm_ln_g = (const float*)d_in[10];
    const float* ssm_ln_b = (const float*)d_in[11];
    const float* xp_w     = (const float*)d_in[12];
    const float* xp_b     = (const float*)d_in[13];
    const float* dt_w     = (const float*)d_in[14];
    const float* dt_b     = (const float*)d_in[15];
    const float* A_log    = (const float*)d_in[16];
    const float* B_w      = (const float*)d_in[17];
    const float* C_w      = (const float*)d_in[18];
    const float* D_param  = (const float*)d_in[19];
    const float* out_w    = (const float*)d_in[20];
    const float* out_b    = (const float*)d_in[21];
    const float* mlp_w1   = (const float*)d_in[22];
    const float* mlp_b1   = (const float*)d_in[23];
    const float* mlp_w2   = (const float*)d_in[24];
    const float* mlp_b2   = (const float*)d_in[25];
    const float* aL       = (const float*)d_in[26];
    const float* aS       = (const float*)d_in[27];
    const float* aM       = (const float*)d_in[28];
    float* out = (float*)d_out;

    // 1. prep: weight concat + tf32 conversion (covers HID*DIM = 147456 elems)
    k_prep<<<576, 256>>>(dt_w, B_w, C_w, xp_w, dt_b, xp_b, A_log, out_w, mlp_w1, mlp_w2);

    // 2. LN1 + ssm_ln
    k_ln<0><<<TOK, DIM>>>(x, ln1_g, ln1_b, ssm_ln_g, ssm_ln_b);

    // 3. projections: [TOK,192] x [256,192]^T -> g_proj
    k_mma<0, 256, 192><<<dim3(256/64, TOK/128), 128>>>(nullptr, nullptr, nullptr, nullptr);

    // 4. chunked scan
    k_scan1<<<NB*NCH, ST>>>();
    k_scan2<<<NB, ST>>>();
    k_scan3<<<NB*NCH, ST>>>();

    // 5. out projection + D*xn1 -> g_ssm
    k_mma<1, 192, 64><<<dim3(192/64, TOK/128), 128>>>(out_b, nullptr, D_param, nullptr);

    // 6. depthwise conv + BN + residual combine -> g_xr (NCHW)
    k_combine<<<dim3(64, DIM, NB), 64>>>(x, dw_w, bn_g, bn_b, bn_rm, bn_rv, aL, aS);

    // 7. LN2 -> g_xn3
    k_ln<1><<<TOK, DIM>>>(nullptr, ln2_g, ln2_b, nullptr, nullptr);

    // 8. MLP fc1 + gelu -> g_hid
    k_mma<2, HID, 192><<<dim3(HID/64, TOK/128), 128>>>(mlp_b1, nullptr, nullptr, nullptr);

    // 9. MLP fc2 + final residual -> d_out (NCHW)
    k_mma<3, 192, HID><<<dim3(192/64, TOK/128), 128>>>(mlp_b2, out, nullptr, aM);
}

// round 3
// speedup vs baseline: 2.4567x; 1.3488x over previous
#include <cuda_runtime.h>
#include <math.h>
#include <stdint.h>

// ---------------- problem constants ----------------
#define NB   8
#define DIM  192
#define ST   64
#define HWSZ 4096            // 64*64
#define TOK  (NB*HWSZ)       // 32768
#define HID  768
#define CHL  32              // scan chunk length
#define NCH  (HWSZ/CHL)      // 128 chunks per batch sequence

// ---------------- scratch (device globals; no allocation) ----------------
__device__ float g_xn1[TOK*DIM];     // LN1(x) fp32
__device__ float g_xn2[TOK*DIM];     // ssm_ln(LN1(x)), tf32-rounded
__device__ float g_proj[TOK*256];    // [dt | B | C | xp] projections
__device__ float g_Av[TOK*ST];       // discretized A
__device__ float g_BX[TOK*ST];       // delta*B*x
__device__ float g_h[TOK*ST];        // local scan states
__device__ float g_yh[TOK*ST];       // C * h, tf32-rounded
__device__ float g_ssm[(size_t)TOK*DIM]; // ssm branch output (NCHW!)
__device__ float g_xr[(size_t)TOK*DIM];  // residual (NCHW)
__device__ float g_xn3[TOK*DIM];     // LN2(xr), tf32 (token-major)
__device__ float g_hid[(size_t)TOK*HID]; // MLP hidden, tf32
__device__ float g_wcat[256*DIM];    // concat weights, tf32
__device__ float g_wout[DIM*ST];     // out_w tf32
__device__ float g_w1[HID*DIM];      // mlp_w1 tf32
__device__ float g_w2[DIM*HID];      // mlp_w2 tf32
__device__ float g_bias256[256];
__device__ float g_Aneg[ST];
__device__ float g_P[NB*NCH*ST];
__device__ float g_hend[NB*NCH*ST];
__device__ float g_hin[NB*NCH*ST];

// ---------------- helpers ----------------
__device__ __forceinline__ float tf32r(float x)
{
    uint32_t u;
    asm("cvt.rna.tf32.f32 %0, %1;" : "=r"(u) : "f"(x));
    return __uint_as_float(u);
}

__device__ __forceinline__ void cp16(void* dst_smem, const void* src)
{
    uint32_t d = (uint32_t)__cvta_generic_to_shared(dst_smem);
    asm volatile("cp.async.cg.shared.global [%0], [%1], 16;" :: "r"(d), "l"(src));
}
__device__ __forceinline__ void cp_commit() { asm volatile("cp.async.commit_group;"); }
template<int W> __device__ __forceinline__ void cp_wait() { asm volatile("cp.async.wait_group %0;" :: "n"(W)); }

// ---------------- prep: weight concat + tf32 + bias + A ----------------
__global__ void k_prep(const float* __restrict__ dt_w, const float* __restrict__ B_w,
                       const float* __restrict__ C_w,  const float* __restrict__ xp_w,
                       const float* __restrict__ dt_b, const float* __restrict__ xp_b,
                       const float* __restrict__ A_log, const float* __restrict__ out_w,
                       const float* __restrict__ mlp_w1, const float* __restrict__ mlp_w2)
{
    int i = blockIdx.x * blockDim.x + threadIdx.x;
    if (i < 256*DIM) {
        int n = i / DIM, k = i - n*DIM;
        float v;
        if      (n < 64)  v = dt_w[n*DIM + k];
        else if (n < 128) v = B_w[(n-64)*DIM + k];
        else if (n < 192) v = C_w[(n-128)*DIM + k];
        else              v = xp_w[(n-192)*DIM + k];
        g_wcat[i] = tf32r(v);
    }
    if (i < DIM*ST)  g_wout[i] = tf32r(out_w[i]);
    if (i < HID*DIM) { g_w1[i] = tf32r(mlp_w1[i]); g_w2[i] = tf32r(mlp_w2[i]); }
    if (i < 256) {
        float b = 0.f;
        if (i < 64)        b = dt_b[i];
        else if (i >= 192) b = xp_b[i-192];
        g_bias256[i] = b;
    }
    if (i < ST) g_Aneg[i] = -expf(A_log[i]);
}

// ---------------- LayerNorm: coalesced tile version ----------------
// Block: 1024 threads, 32 tokens x 192 channels.
// MODE 0: x (NCHW) -> g_xn1 (fp32) + g_xn2 (tf32, second LN)
// MODE 1: g_xr (NCHW) -> g_xn3 (tf32)
template<int MODE>
__global__ void __launch_bounds__(1024) k_ln(const float* __restrict__ xin,
                     const float* __restrict__ g1, const float* __restrict__ b1,
                     const float* __restrict__ g2, const float* __restrict__ b2)
{
    __shared__ float s[192*33];
    int tid = threadIdx.x;
    int tok0 = blockIdx.x * 32;
    int b = tok0 >> 12, hw0 = tok0 & (HWSZ-1);
    const float* src = (MODE == 0) ? xin : g_xr;

    // coalesced load: channel-major NCHW tile -> smem [c][j]
    #pragma unroll
    for (int i = 0; i < 6; i++) {
        int idx = tid + 1024*i;
        int c = idx >> 5, j = idx & 31;
        s[c*33 + j] = src[((size_t)(b*DIM + c))*HWSZ + hw0 + j];
    }
    __syncthreads();

    // warp-per-token reduction: warp w = token, lane l covers c = l+32i
    int w = tid >> 5, l = tid & 31;
    float v[6], sum = 0.f, sq = 0.f;
    #pragma unroll
    for (int i = 0; i < 6; i++) {
        v[i] = s[(l + 32*i)*33 + w];
        sum += v[i]; sq += v[i]*v[i];
    }
    #pragma unroll
    for (int o = 16; o > 0; o >>= 1) {
        sum += __shfl_xor_sync(0xffffffffu, sum, o);
        sq  += __shfl_xor_sync(0xffffffffu, sq,  o);
    }
    float mean = sum * (1.f/DIM);
    float var  = sq  * (1.f/DIM) - mean*mean;
    float rs = rsqrtf(var + 1e-5f);
    float y[6];
    #pragma unroll
    for (int i = 0; i < 6; i++) {
        int c = l + 32*i;
        y[i] = (v[i] - mean) * rs * g1[c] + b1[c];
    }
    __syncthreads();
    #pragma unroll
    for (int i = 0; i < 6; i++) s[(l + 32*i)*33 + w] = y[i];
    __syncthreads();
    // coalesced writeout token-major
    {
        float* dst = (MODE == 0) ? g_xn1 : g_xn3;
        #pragma unroll
        for (int i = 0; i < 6; i++) {
            int idx = tid + 1024*i;
            int tok = idx / 192, c = idx - tok*192;
            float val = s[c*33 + tok];
            dst[(size_t)(tok0 + tok)*DIM + c] = (MODE == 0) ? val : tf32r(val);
        }
    }
    if (MODE == 0) {
        // second LN on y
        float s2a = 0.f, s2b = 0.f;
        #pragma unroll
        for (int i = 0; i < 6; i++) { s2a += y[i]; s2b += y[i]*y[i]; }
        #pragma unroll
        for (int o = 16; o > 0; o >>= 1) {
            s2a += __shfl_xor_sync(0xffffffffu, s2a, o);
            s2b += __shfl_xor_sync(0xffffffffu, s2b, o);
        }
        float m2 = s2a * (1.f/DIM);
        float v2 = s2b * (1.f/DIM) - m2*m2;
        float rs2 = rsqrtf(v2 + 1e-5f);
        __syncthreads();
        #pragma unroll
        for (int i = 0; i < 6; i++) {
            int c = l + 32*i;
            s[(l + 32*i)*33 + w] = tf32r((y[i] - m2) * rs2 * g2[c] + b2[c]);
        }
        __syncthreads();
        #pragma unroll
        for (int i = 0; i < 6; i++) {
            int idx = tid + 1024*i;
            int tok = idx / 192, c = idx - tok*192;
            g_xn2[(size_t)(tok0 + tok)*DIM + c] = s[c*33 + tok];
        }
    }
}

// ---------------- SSM elementwise precompute (fully parallel) ----------------
__global__ void k_ssmpre()
{
    int idx = blockIdx.x * blockDim.x + threadIdx.x;  // TOK*ST
    int tok = idx >> 6, s = idx & 63;
    const float* p = g_proj + (size_t)tok*256;
    float dt = p[s], Bv = p[64+s], xv = p[192+s];
    float An = g_Aneg[s];
    float sp = fmaxf(dt, 0.f) + log1pf(expf(-fabsf(dt)));
    float delta = sp * 0.01f + 1e-4f;
    float dA = fminf(fmaxf(delta * An, -10.f), -1e-4f);
    float Av = fminf(fmaxf(expf(dA), 0.001f), 0.999f);
    g_Av[idx] = Av;
    g_BX[idx] = delta * Bv * xv;
}

// ---------------- scan pass 1: local chunk scans ----------------
__global__ void k_scan1()
{
    int s = threadIdx.x;
    int bidx = blockIdx.x;            // NB*NCH
    int b = bidx >> 7, ch = bidx & (NCH-1);
    float h = 0.f, P = 1.f;
    int tok0 = b*HWSZ + ch*CHL;
    bool c0 = (ch == 0);
    #pragma unroll 8
    for (int t = 0; t < CHL; t++) {
        size_t o = (size_t)(tok0 + t)*ST + s;
        float Av = g_Av[o], BX = g_BX[o];
        h = (c0 && t == 0) ? BX : Av*(h + BX);
        P *= Av;
        g_h[o] = h;
    }
    g_P[bidx*ST + s] = P;
    g_hend[bidx*ST + s] = h;
}

// ---------------- scan pass 2: chunk carry prefix ----------------
__global__ void k_scan2()
{
    int s = threadIdx.x;
    int b = blockIdx.x;
    float hin = 0.f;
    for (int ch = 0; ch < NCH; ch++) {
        int i = (b*NCH + ch)*ST + s;
        g_hin[i] = hin;
        hin = g_P[i]*hin + g_hend[i];
    }
}

// ---------------- scan pass 3: fix-up + y = C*h ----------------
__global__ void k_scan3()
{
    int s = threadIdx.x;
    int bidx = blockIdx.x;
    int b = bidx >> 7, ch = bidx & (NCH-1);
    float hin = g_hin[bidx*ST + s];
    float P = 1.f;
    int tok0 = b*HWSZ + ch*CHL;
    #pragma unroll 8
    for (int t = 0; t < CHL; t++) {
        size_t o = (size_t)(tok0 + t)*ST + s;
        float Av = g_Av[o];
        P *= Av;
        float hf = g_h[o] + P*hin;
        float Cv = g_proj[(size_t)(tok0 + t)*256 + 128 + s];
        g_yh[o] = tf32r(Cv * hf);
    }
}

// ---------------- depthwise conv + BN + residual combine (NCHW) ----------------
__global__ void __launch_bounds__(256) k_combine(
    const float* __restrict__ x, const float* __restrict__ dw,
    const float* __restrict__ bn_g, const float* __restrict__ bn_b,
    const float* __restrict__ bn_rm, const float* __restrict__ bn_rv,
    const float* __restrict__ aL, const float* __restrict__ aS)
{
    int tid = threadIdx.x;
    int w = tid & 63, hs = tid >> 6;
    int h = blockIdx.x*4 + hs;
    int c = blockIdx.y;
    int b = blockIdx.z;
    const float* xb = x + ((size_t)(b*DIM + c))*HWSZ;
    const float* wk = dw + c*9;
    float acc = 0.f;
    #pragma unroll
    for (int kh = 0; kh < 3; kh++) {
        int hh = h + kh - 1;
        if (hh < 0 || hh >= 64) continue;
        #pragma unroll
        for (int kw = 0; kw < 3; kw++) {
            int ww = w + kw - 1;
            if (ww < 0 || ww >= 64) continue;
            acc += xb[hh*64 + ww] * wk[kh*3 + kw];
        }
    }
    float scale = bn_g[c] * rsqrtf(bn_rv[c] + 1e-5f);
    float local = (acc - bn_rm[c]) * scale + bn_b[c];
    size_t base = ((size_t)(b*DIM + c))*HWSZ + h*64 + w;
    g_xr[base] = xb[h*64 + w] + aL[0]*local + aS[0]*g_ssm[base];
}

// ---------------- tf32 mma helper ----------------
__device__ __forceinline__ void mma_tf32(float* c, const uint32_t* a, const uint32_t* b)
{
    asm volatile(
        "mma.sync.aligned.m16n8k8.row.col.f32.tf32.tf32.f32 "
        "{%0,%1,%2,%3}, {%4,%5,%6,%7}, {%8,%9}, {%0,%1,%2,%3};"
        : "+f"(c[0]), "+f"(c[1]), "+f"(c[2]), "+f"(c[3])
        : "r"(a[0]), "r"(a[1]), "r"(a[2]), "r"(a[3]), "r"(b[0]), "r"(b[1]));
}

// ---------------- TF32 tensor-core GEMM, cp.async 2-stage ----------------
// C[M,N] = A[M,K] @ Bw[N,K]^T. Block 128 thr (4 warps), BM=128, BN=64, BK=32.
// EPI 0: A=g_xn2, B=g_wcat, bias=g_bias256 -> g_proj (token-major)
// EPI 1: A=g_yh,  B=g_wout, bias + clip(D)*g_xn1 -> g_ssm (NCHW, smem transpose)
// EPI 2: A=g_xn3, B=g_w1,   bias + gelu -> g_hid (tf32, token-major)
// EPI 3: A=g_hid, B=g_w2,   bias; out = g_xr + alpha*v -> d_out (NCHW, smem transpose)
#define SMEM_GEMM_BYTES 55296
template<int EPI, int N, int K>
__global__ void __launch_bounds__(128) k_mma(const float* __restrict__ bias,
                                             float* __restrict__ Cout,
                                             const float* __restrict__ Dp,
                                             const float* __restrict__ alpha)
{
    extern __shared__ float sm[];
    // stage s: A at s*(128*36), B at 2*128*36 + s*(64*36)
    const float* A  = (EPI == 0) ? g_xn2 : (EPI == 1) ? g_yh : (EPI == 2) ? g_xn3 : g_hid;
    const float* Bp = (EPI == 0) ? g_wcat : (EPI == 1) ? g_wout : (EPI == 2) ? g_w1 : g_w2;
    const float* bp = (EPI == 0) ? g_bias256 : bias;

    int tid = threadIdx.x;
    int warp = tid >> 5, lane = tid & 31;
    int g = lane >> 2, t4 = lane & 3;
    int row0 = blockIdx.y * 128, col0 = blockIdx.x * 64;
    int m0 = warp * 32;

    float acc[2][8][4];
    #pragma unroll
    for (int mi = 0; mi < 2; mi++)
        #pragma unroll
        for (int ni = 0; ni < 8; ni++)
            #pragma unroll
            for (int e = 0; e < 4; e++) acc[mi][ni][e] = 0.f;

    const int NK = K / 32;

    // async load of one k-slab into stage st
    auto load_slab = [&](int kt, int st) {
        float* As = sm + st*(128*36);
        float* Bs = sm + 2*(128*36) + st*(64*36);
        int k0 = kt * 32;
        #pragma unroll
        for (int i = 0; i < 8; i++) {
            int f = tid + 128*i;
            int m = f >> 3, kq = f & 7;
            cp16(&As[m*36 + kq*4], A + (size_t)(row0 + m)*K + k0 + kq*4);
        }
        #pragma unroll
        for (int i = 0; i < 4; i++) {
            int f = tid + 128*i;
            int n = f >> 3, kq = f & 7;
            cp16(&Bs[n*36 + kq*4], Bp + (size_t)(col0 + n)*K + k0 + kq*4);
        }
    };

    load_slab(0, 0);
    cp_commit();

    for (int kt = 0; kt < NK; kt++) {
        int cur = kt & 1;
        if (kt + 1 < NK) {
            load_slab(kt + 1, (kt + 1) & 1);
            cp_commit();
            cp_wait<1>();
        } else {
            cp_wait<0>();
        }
        __syncthreads();

        const uint32_t* As = reinterpret_cast<const uint32_t*>(sm + cur*(128*36));
        const uint32_t* Bs = reinterpret_cast<const uint32_t*>(sm + 2*(128*36) + cur*(64*36));
        #pragma unroll
        for (int k8 = 0; k8 < 4; k8++) {
            int kb = k8 * 8;
            uint32_t a[2][4], b[8][2];
            #pragma unroll
            for (int mi = 0; mi < 2; mi++) {
                int r = m0 + mi*16 + g;
                a[mi][0] = As[r*36 + kb + t4];
                a[mi][1] = As[(r+8)*36 + kb + t4];
                a[mi][2] = As[r*36 + kb + t4 + 4];
                a[mi][3] = As[(r+8)*36 + kb + t4 + 4];
            }
            #pragma unroll
            for (int ni = 0; ni < 8; ni++) {
                int c = ni*8 + g;
                b[ni][0] = Bs[c*36 + kb + t4];
                b[ni][1] = Bs[c*36 + kb + t4 + 4];
            }
            #pragma unroll
            for (int mi = 0; mi < 2; mi++)
                #pragma unroll
                for (int ni = 0; ni < 8; ni++)
                    mma_tf32(acc[mi][ni], a[mi], b[ni]);
        }
        __syncthreads();
    }

    if (EPI == 0 || EPI == 2) {
        // token-major direct writeout
        #pragma unroll
        for (int mi = 0; mi < 2; mi++)
            #pragma unroll
            for (int ni = 0; ni < 8; ni++)
                #pragma unroll
                for (int e = 0; e < 4; e++) {
                    int m = row0 + m0 + mi*16 + g + ((e >> 1) << 3);
                    int n = col0 + ni*8 + t4*2 + (e & 1);
                    float v = acc[mi][ni][e] + bp[n];
                    if (EPI == 2) {
                        v = 0.5f * v * (1.f + erff(v * 0.7071067811865476f));
                        g_hid[(size_t)m*N + n] = tf32r(v);
                    } else {
                        g_proj[(size_t)m*N + n] = v;
                    }
                }
    } else {
        // NCHW writeout via smem transpose: T[n_local][m_local], pitch 129
        float* T = sm;
        #pragma unroll
        for (int mi = 0; mi < 2; mi++)
            #pragma unroll
            for (int ni = 0; ni < 8; ni++)
                #pragma unroll
                for (int e = 0; e < 4; e++) {
                    int ml = m0 + mi*16 + g + ((e >> 1) << 3);
                    int nl = ni*8 + t4*2 + (e & 1);
                    float v = acc[mi][ni][e] + bp[col0 + nl];
                    if (EPI == 1) {
                        int n = col0 + nl;
                        float d = fminf(fmaxf(Dp[n], -2.f), 2.f);
                        v += d * g_xn1[(size_t)(row0 + ml)*DIM + n];
                    }
                    T[nl*129 + ml] = v;
                }
        __syncthreads();
        int bb = row0 >> 12, hw0 = row0 & (HWSZ-1);
        float aM = (EPI == 3) ? alpha[0] : 0.f;
        #pragma unroll
        for (int i = 0; i < 64; i++) {
            int idx = tid + 128*i;
            int nl = idx >> 7, ml = idx & 127;
            size_t adr = ((size_t)(bb*DIM + col0 + nl))*HWSZ + hw0 + ml;
            if (EPI == 1) g_ssm[adr] = T[nl*129 + ml];
            else          Cout[adr] = g_xr[adr] + aM * T[nl*129 + ml];
        }
    }
}

// ---------------- launch ----------------
extern "C" void kernel_launch(void* const* d_in, const int* in_sizes, int n_in,
                              void* d_out, int out_size)
{
    const float* x        = (const float*)d_in[0];
    const float* ln1_g    = (const float*)d_in[1];
    const float* ln1_b    = (const float*)d_in[2];
    const float* ln2_g    = (const float*)d_in[3];
    const float* ln2_b    = (const float*)d_in[4];
    const float* dw_w     = (const float*)d_in[5];
    const float* bn_g     = (const float*)d_in[6];
    const float* bn_b     = (const float*)d_in[7];
    const float* bn_rm    = (const float*)d_in[8];
    const float* bn_rv    = (const float*)d_in[9];
    const float* ssm_ln_g = (const float*)d_in[10];
    const float* ssm_ln_b = (const float*)d_in[11];
    const float* xp_w     = (const float*)d_in[12];
    const float* xp_b     = (const float*)d_in[13];
    const float* dt_w     = (const float*)d_in[14];
    const float* dt_b     = (const float*)d_in[15];
    const float* A_log    = (const float*)d_in[16];
    const float* B_w      = (const float*)d_in[17];
    const float* C_w      = (const float*)d_in[18];
    const float* D_param  = (const float*)d_in[19];
    const float* out_w    = (const float*)d_in[20];
    const float* out_b    = (const float*)d_in[21];
    const float* mlp_w1   = (const float*)d_in[22];
    const float* mlp_b1   = (const float*)d_in[23];
    const float* mlp_w2   = (const float*)d_in[24];
    const float* mlp_b2   = (const float*)d_in[25];
    const float* aL       = (const float*)d_in[26];
    const float* aS       = (const float*)d_in[27];
    const float* aM       = (const float*)d_in[28];
    float* out = (float*)d_out;

    // allow >48KB dynamic smem for the GEMM kernels (immediate API, not captured)
    cudaFuncSetAttribute(k_mma<0,256,192>, cudaFuncAttributeMaxDynamicSharedMemorySize, SMEM_GEMM_BYTES);
    cudaFuncSetAttribute(k_mma<1,192,64>,  cudaFuncAttributeMaxDynamicSharedMemorySize, SMEM_GEMM_BYTES);
    cudaFuncSetAttribute(k_mma<2,HID,192>, cudaFuncAttributeMaxDynamicSharedMemorySize, SMEM_GEMM_BYTES);
    cudaFuncSetAttribute(k_mma<3,192,HID>, cudaFuncAttributeMaxDynamicSharedMemorySize, SMEM_GEMM_BYTES);

    // 1. prep
    k_prep<<<576, 256>>>(dt_w, B_w, C_w, xp_w, dt_b, xp_b, A_log, out_w, mlp_w1, mlp_w2);

    // 2. LN1 + ssm_ln (coalesced)
    k_ln<0><<<TOK/32, 1024>>>(x, ln1_g, ln1_b, ssm_ln_g, ssm_ln_b);

    // 3. projections
    k_mma<0, 256, 192><<<dim3(256/64, TOK/128), 128, SMEM_GEMM_BYTES>>>(nullptr, nullptr, nullptr, nullptr);

    // 4. scan: elementwise precompute + 3-pass chunked scan
    k_ssmpre<<<TOK*ST/256, 256>>>();
    k_scan1<<<NB*NCH, ST>>>();
    k_scan2<<<NB, ST>>>();
    k_scan3<<<NB*NCH, ST>>>();

    // 5. out projection + D*xn1 -> g_ssm (NCHW)
    k_mma<1, 192, 64><<<dim3(192/64, TOK/128), 128, SMEM_GEMM_BYTES>>>(out_b, nullptr, D_param, nullptr);

    // 6. conv + BN + residual combine -> g_xr (NCHW)
    k_combine<<<dim3(16, DIM, NB), 256>>>(x, dw_w, bn_g, bn_b, bn_rm, bn_rv, aL, aS);

    // 7. LN2
    k_ln<1><<<TOK/32, 1024>>>(nullptr, ln2_g, ln2_b, nullptr, nullptr);

    // 8. MLP fc1 + gelu
    k_mma<2, HID, 192><<<dim3(HID/64, TOK/128), 128, SMEM_GEMM_BYTES>>>(mlp_b1, nullptr, nullptr, nullptr);

    // 9. MLP fc2 + final residual -> d_out (NCHW)
    k_mma<3, 192, HID><<<dim3(192/64, TOK/128), 128, SMEM_GEMM_BYTES>>>(mlp_b2, out, nullptr, aM);
}

// round 4
// speedup vs baseline: 2.4582x; 1.0006x over previous
#include <cuda_runtime.h>
#include <math.h>
#include <stdint.h>

// ---------------- problem constants ----------------
#define NB   8
#define DIM  192
#define ST   64
#define HWSZ 4096            // 64*64
#define TOK  (NB*HWSZ)       // 32768
#define HID  768
#define CHL  32              // scan chunk length
#define NCH  (HWSZ/CHL)      // 128 chunks per batch sequence

// ---------------- scratch (device globals; no allocation) ----------------
__device__ float g_xn1[TOK*DIM];     // LN1(x) fp32
__device__ float g_xn2[TOK*DIM];     // ssm_ln(LN1(x)), tf32-rounded
__device__ float g_proj[TOK*256];    // [dt | B | C | xp] projections
__device__ float g_Av[TOK*ST];       // discretized A
__device__ float g_BX[TOK*ST];       // delta*B*x
__device__ float g_h[TOK*ST];        // local scan states
__device__ float g_yh[TOK*ST];       // C * h, tf32-rounded
__device__ float g_ssm[(size_t)TOK*DIM]; // ssm branch output (NCHW!)
__device__ float g_xr[(size_t)TOK*DIM];  // residual (NCHW)
__device__ float g_xn3[TOK*DIM];     // LN2(xr), tf32 (token-major)
__device__ float g_hid[(size_t)TOK*HID]; // MLP hidden, tf32
__device__ float g_wcat[256*DIM];    // concat weights, tf32
__device__ float g_wout[DIM*ST];     // out_w tf32
__device__ float g_w1[HID*DIM];      // mlp_w1 tf32
__device__ float g_w2[DIM*HID];      // mlp_w2 tf32
__device__ float g_bias256[256];
__device__ float g_Aneg[ST];
__device__ float g_P[NB*NCH*ST];
__device__ float g_hend[NB*NCH*ST];
__device__ float g_hin[NB*NCH*ST];

// ---------------- helpers ----------------
__device__ __forceinline__ float tf32r(float x)
{
    uint32_t u;
    asm("cvt.rna.tf32.f32 %0, %1;" : "=r"(u) : "f"(x));
    return __uint_as_float(u);
}

__device__ __forceinline__ void cp16(void* dst_smem, const void* src)
{
    uint32_t d = (uint32_t)__cvta_generic_to_shared(dst_smem);
    asm volatile("cp.async.cg.shared.global [%0], [%1], 16;" :: "r"(d), "l"(src));
}
__device__ __forceinline__ void cp_commit() { asm volatile("cp.async.commit_group;"); }
template<int W> __device__ __forceinline__ void cp_wait() { asm volatile("cp.async.wait_group %0;" :: "n"(W)); }

// ---------------- prep: weight concat + tf32 + bias + A ----------------
__global__ void k_prep(const float* __restrict__ dt_w, const float* __restrict__ B_w,
                       const float* __restrict__ C_w,  const float* __restrict__ xp_w,
                       const float* __restrict__ dt_b, const float* __restrict__ xp_b,
                       const float* __restrict__ A_log, const float* __restrict__ out_w,
                       const float* __restrict__ mlp_w1, const float* __restrict__ mlp_w2)
{
    int i = blockIdx.x * blockDim.x + threadIdx.x;
    if (i < 256*DIM) {
        int n = i / DIM, k = i - n*DIM;
        float v;
        if      (n < 64)  v = dt_w[n*DIM + k];
        else if (n < 128) v = B_w[(n-64)*DIM + k];
        else if (n < 192) v = C_w[(n-128)*DIM + k];
        else              v = xp_w[(n-192)*DIM + k];
        g_wcat[i] = tf32r(v);
    }
    if (i < DIM*ST)  g_wout[i] = tf32r(out_w[i]);
    if (i < HID*DIM) { g_w1[i] = tf32r(mlp_w1[i]); g_w2[i] = tf32r(mlp_w2[i]); }
    if (i < 256) {
        float b = 0.f;
        if (i < 64)        b = dt_b[i];
        else if (i >= 192) b = xp_b[i-192];
        g_bias256[i] = b;
    }
    if (i < ST) g_Aneg[i] = -expf(A_log[i]);
}

// ---------------- LayerNorm: coalesced tile version ----------------
// Block: 1024 threads, 32 tokens x 192 channels.
// MODE 0: x (NCHW) -> g_xn1 (fp32) + g_xn2 (tf32, second LN)
// MODE 1: g_xr (NCHW) -> g_xn3 (tf32)
template<int MODE>
__global__ void __launch_bounds__(1024) k_ln(const float* __restrict__ xin,
                     const float* __restrict__ g1, const float* __restrict__ b1,
                     const float* __restrict__ g2, const float* __restrict__ b2)
{
    __shared__ float s[192*33];
    int tid = threadIdx.x;
    int tok0 = blockIdx.x * 32;
    int b = tok0 >> 12, hw0 = tok0 & (HWSZ-1);
    const float* src = (MODE == 0) ? xin : g_xr;

    // coalesced load: channel-major NCHW tile -> smem [c][j]
    #pragma unroll
    for (int i = 0; i < 6; i++) {
        int idx = tid + 1024*i;
        int c = idx >> 5, j = idx & 31;
        s[c*33 + j] = src[((size_t)(b*DIM + c))*HWSZ + hw0 + j];
    }
    __syncthreads();

    // warp-per-token reduction: warp w = token, lane l covers c = l+32i
    int w = tid >> 5, l = tid & 31;
    float v[6], sum = 0.f, sq = 0.f;
    #pragma unroll
    for (int i = 0; i < 6; i++) {
        v[i] = s[(l + 32*i)*33 + w];
        sum += v[i]; sq += v[i]*v[i];
    }
    #pragma unroll
    for (int o = 16; o > 0; o >>= 1) {
        sum += __shfl_xor_sync(0xffffffffu, sum, o);
        sq  += __shfl_xor_sync(0xffffffffu, sq,  o);
    }
    float mean = sum * (1.f/DIM);
    float var  = sq  * (1.f/DIM) - mean*mean;
    float rs = rsqrtf(var + 1e-5f);
    float y[6];
    #pragma unroll
    for (int i = 0; i < 6; i++) {
        int c = l + 32*i;
        y[i] = (v[i] - mean) * rs * g1[c] + b1[c];
    }
    __syncthreads();
    #pragma unroll
    for (int i = 0; i < 6; i++) s[(l + 32*i)*33 + w] = y[i];
    __syncthreads();
    // coalesced writeout token-major
    {
        float* dst = (MODE == 0) ? g_xn1 : g_xn3;
        #pragma unroll
        for (int i = 0; i < 6; i++) {
            int idx = tid + 1024*i;
            int tok = idx / 192, c = idx - tok*192;
            float val = s[c*33 + tok];
            dst[(size_t)(tok0 + tok)*DIM + c] = (MODE == 0) ? val : tf32r(val);
        }
    }
    if (MODE == 0) {
        // second LN on y
        float s2a = 0.f, s2b = 0.f;
        #pragma unroll
        for (int i = 0; i < 6; i++) { s2a += y[i]; s2b += y[i]*y[i]; }
        #pragma unroll
        for (int o = 16; o > 0; o >>= 1) {
            s2a += __shfl_xor_sync(0xffffffffu, s2a, o);
            s2b += __shfl_xor_sync(0xffffffffu, s2b, o);
        }
        float m2 = s2a * (1.f/DIM);
        float v2 = s2b * (1.f/DIM) - m2*m2;
        float rs2 = rsqrtf(v2 + 1e-5f);
        __syncthreads();
        #pragma unroll
        for (int i = 0; i < 6; i++) {
            int c = l + 32*i;
            s[(l + 32*i)*33 + w] = tf32r((y[i] - m2) * rs2 * g2[c] + b2[c]);
        }
        __syncthreads();
        #pragma unroll
        for (int i = 0; i < 6; i++) {
            int idx = tid + 1024*i;
            int tok = idx / 192, c = idx - tok*192;
            g_xn2[(size_t)(tok0 + tok)*DIM + c] = s[c*33 + tok];
        }
    }
}

// ---------------- SSM elementwise precompute (fully parallel) ----------------
__global__ void k_ssmpre()
{
    int idx = blockIdx.x * blockDim.x + threadIdx.x;  // TOK*ST
    int tok = idx >> 6, s = idx & 63;
    const float* p = g_proj + (size_t)tok*256;
    float dt = p[s], Bv = p[64+s], xv = p[192+s];
    float An = g_Aneg[s];
    float sp = fmaxf(dt, 0.f) + log1pf(expf(-fabsf(dt)));
    float delta = sp * 0.01f + 1e-4f;
    float dA = fminf(fmaxf(delta * An, -10.f), -1e-4f);
    float Av = fminf(fmaxf(expf(dA), 0.001f), 0.999f);
    g_Av[idx] = Av;
    g_BX[idx] = delta * Bv * xv;
}

// ---------------- scan pass 1: local chunk scans ----------------
__global__ void k_scan1()
{
    int s = threadIdx.x;
    int bidx = blockIdx.x;            // NB*NCH
    int b = bidx >> 7, ch = bidx & (NCH-1);
    float h = 0.f, P = 1.f;
    int tok0 = b*HWSZ + ch*CHL;
    bool c0 = (ch == 0);
    #pragma unroll 8
    for (int t = 0; t < CHL; t++) {
        size_t o = (size_t)(tok0 + t)*ST + s;
        float Av = g_Av[o], BX = g_BX[o];
        h = (c0 && t == 0) ? BX : Av*(h + BX);
        P *= Av;
        g_h[o] = h;
    }
    g_P[bidx*ST + s] = P;
    g_hend[bidx*ST + s] = h;
}

// ---------------- scan pass 2: chunk carry prefix ----------------
__global__ void k_scan2()
{
    int s = threadIdx.x;
    int b = blockIdx.x;
    float hin = 0.f;
    for (int ch = 0; ch < NCH; ch++) {
        int i = (b*NCH + ch)*ST + s;
        g_hin[i] = hin;
        hin = g_P[i]*hin + g_hend[i];
    }
}

// ---------------- scan pass 3: fix-up + y = C*h ----------------
__global__ void k_scan3()
{
    int s = threadIdx.x;
    int bidx = blockIdx.x;
    int b = bidx >> 7, ch = bidx & (NCH-1);
    float hin = g_hin[bidx*ST + s];
    float P = 1.f;
    int tok0 = b*HWSZ + ch*CHL;
    #pragma unroll 8
    for (int t = 0; t < CHL; t++) {
        size_t o = (size_t)(tok0 + t)*ST + s;
        float Av = g_Av[o];
        P *= Av;
        float hf = g_h[o] + P*hin;
        float Cv = g_proj[(size_t)(tok0 + t)*256 + 128 + s];
        g_yh[o] = tf32r(Cv * hf);
    }
}

// ---------------- depthwise conv + BN + residual combine (NCHW) ----------------
__global__ void __launch_bounds__(256) k_combine(
    const float* __restrict__ x, const float* __restrict__ dw,
    const float* __restrict__ bn_g, const float* __restrict__ bn_b,
    const float* __restrict__ bn_rm, const float* __restrict__ bn_rv,
    const float* __restrict__ aL, const float* __restrict__ aS)
{
    int tid = threadIdx.x;
    int w = tid & 63, hs = tid >> 6;
    int h = blockIdx.x*4 + hs;
    int c = blockIdx.y;
    int b = blockIdx.z;
    const float* xb = x + ((size_t)(b*DIM + c))*HWSZ;
    const float* wk = dw + c*9;
    float acc = 0.f;
    #pragma unroll
    for (int kh = 0; kh < 3; kh++) {
        int hh = h + kh - 1;
        if (hh < 0 || hh >= 64) continue;
        #pragma unroll
        for (int kw = 0; kw < 3; kw++) {
            int ww = w + kw - 1;
            if (ww < 0 || ww >= 64) continue;
            acc += xb[hh*64 + ww] * wk[kh*3 + kw];
        }
    }
    float scale = bn_g[c] * rsqrtf(bn_rv[c] + 1e-5f);
    float local = (acc - bn_rm[c]) * scale + bn_b[c];
    size_t base = ((size_t)(b*DIM + c))*HWSZ + h*64 + w;
    g_xr[base] = xb[h*64 + w] + aL[0]*local + aS[0]*g_ssm[base];
}

// ---------------- tf32 mma helper ----------------
__device__ __forceinline__ void mma_tf32(float* c, const uint32_t* a, const uint32_t* b)
{
    asm volatile(
        "mma.sync.aligned.m16n8k8.row.col.f32.tf32.tf32.f32 "
        "{%0,%1,%2,%3}, {%4,%5,%6,%7}, {%8,%9}, {%0,%1,%2,%3};"
        : "+f"(c[0]), "+f"(c[1]), "+f"(c[2]), "+f"(c[3])
        : "r"(a[0]), "r"(a[1]), "r"(a[2]), "r"(a[3]), "r"(b[0]), "r"(b[1]));
}

// ---------------- TF32 tensor-core GEMM, cp.async 2-stage ----------------
// C[M,N] = A[M,K] @ Bw[N,K]^T. Block 128 thr (4 warps), BM=128, BN=64, BK=32.
// EPI 0: A=g_xn2, B=g_wcat, bias=g_bias256 -> g_proj (token-major)
// EPI 1: A=g_yh,  B=g_wout, bias + clip(D)*g_xn1 -> g_ssm (NCHW, smem transpose)
// EPI 2: A=g_xn3, B=g_w1,   bias + gelu -> g_hid (tf32, token-major)
// EPI 3: A=g_hid, B=g_w2,   bias; out = g_xr + alpha*v -> d_out (NCHW, smem transpose)
#define SMEM_GEMM_BYTES 55296
template<int EPI, int N, int K>
__global__ void __launch_bounds__(128) k_mma(const float* __restrict__ bias,
                                             float* __restrict__ Cout,
                                             const float* __restrict__ Dp,
                                             const float* __restrict__ alpha)
{
    extern __shared__ float sm[];
    // stage s: A at s*(128*36), B at 2*128*36 + s*(64*36)
    const float* A  = (EPI == 0) ? g_xn2 : (EPI == 1) ? g_yh : (EPI == 2) ? g_xn3 : g_hid;
    const float* Bp = (EPI == 0) ? g_wcat : (EPI == 1) ? g_wout : (EPI == 2) ? g_w1 : g_w2;
    const float* bp = (EPI == 0) ? g_bias256 : bias;

    int tid = threadIdx.x;
    int warp = tid >> 5, lane = tid & 31;
    int g = lane >> 2, t4 = lane & 3;
    int row0 = blockIdx.y * 128, col0 = blockIdx.x * 64;
    int m0 = warp * 32;

    float acc[2][8][4];
    #pragma unroll
    for (int mi = 0; mi < 2; mi++)
        #pragma unroll
        for (int ni = 0; ni < 8; ni++)
            #pragma unroll
            for (int e = 0; e < 4; e++) acc[mi][ni][e] = 0.f;

    const int NK = K / 32;

    // async load of one k-slab into stage st
    auto load_slab = [&](int kt, int st) {
        float* As = sm + st*(128*36);
        float* Bs = sm + 2*(128*36) + st*(64*36);
        int k0 = kt * 32;
        #pragma unroll
        for (int i = 0; i < 8; i++) {
            int f = tid + 128*i;
            int m = f >> 3, kq = f & 7;
            cp16(&As[m*36 + kq*4], A + (size_t)(row0 + m)*K + k0 + kq*4);
        }
        #pragma unroll
        for (int i = 0; i < 4; i++) {
            int f = tid + 128*i;
            int n = f >> 3, kq = f & 7;
            cp16(&Bs[n*36 + kq*4], Bp + (size_t)(col0 + n)*K + k0 + kq*4);
        }
    };

    load_slab(0, 0);
    cp_commit();

    for (int kt = 0; kt < NK; kt++) {
        int cur = kt & 1;
        if (kt + 1 < NK) {
            load_slab(kt + 1, (kt + 1) & 1);
            cp_commit();
            cp_wait<1>();
        } else {
            cp_wait<0>();
        }
        __syncthreads();

        const uint32_t* As = reinterpret_cast<const uint32_t*>(sm + cur*(128*36));
        const uint32_t* Bs = reinterpret_cast<const uint32_t*>(sm + 2*(128*36) + cur*(64*36));
        #pragma unroll
        for (int k8 = 0; k8 < 4; k8++) {
            int kb = k8 * 8;
            uint32_t a[2][4], b[8][2];
            #pragma unroll
            for (int mi = 0; mi < 2; mi++) {
                int r = m0 + mi*16 + g;
                a[mi][0] = As[r*36 + kb + t4];
                a[mi][1] = As[(r+8)*36 + kb + t4];
                a[mi][2] = As[r*36 + kb + t4 + 4];
                a[mi][3] = As[(r+8)*36 + kb + t4 + 4];
            }
            #pragma unroll
            for (int ni = 0; ni < 8; ni++) {
                int c = ni*8 + g;
                b[ni][0] = Bs[c*36 + kb + t4];
                b[ni][1] = Bs[c*36 + kb + t4 + 4];
            }
            #pragma unroll
            for (int mi = 0; mi < 2; mi++)
                #pragma unroll
                for (int ni = 0; ni < 8; ni++)
                    mma_tf32(acc[mi][ni], a[mi], b[ni]);
        }
        __syncthreads();
    }

    if (EPI == 0 || EPI == 2) {
        // token-major direct writeout
        #pragma unroll
        for (int mi = 0; mi < 2; mi++)
            #pragma unroll
            for (int ni = 0; ni < 8; ni++)
                #pragma unroll
                for (int e = 0; e < 4; e++) {
                    int m = row0 + m0 + mi*16 + g + ((e >> 1) << 3);
                    int n = col0 + ni*8 + t4*2 + (e & 1);
                    float v = acc[mi][ni][e] + bp[n];
                    if (EPI == 2) {
                        v = 0.5f * v * (1.f + erff(v * 0.7071067811865476f));
                        g_hid[(size_t)m*N + n] = tf32r(v);
                    } else {
                        g_proj[(size_t)m*N + n] = v;
                    }
                }
    } else {
        // NCHW writeout via smem transpose: T[n_local][m_local], pitch 129
        float* T = sm;
        #pragma unroll
        for (int mi = 0; mi < 2; mi++)
            #pragma unroll
            for (int ni = 0; ni < 8; ni++)
                #pragma unroll
                for (int e = 0; e < 4; e++) {
                    int ml = m0 + mi*16 + g + ((e >> 1) << 3);
                    int nl = ni*8 + t4*2 + (e & 1);
                    float v = acc[mi][ni][e] + bp[col0 + nl];
                    if (EPI == 1) {
                        int n = col0 + nl;
                        float d = fminf(fmaxf(Dp[n], -2.f), 2.f);
                        v += d * g_xn1[(size_t)(row0 + ml)*DIM + n];
                    }
                    T[nl*129 + ml] = v;
                }
        __syncthreads();
        int bb = row0 >> 12, hw0 = row0 & (HWSZ-1);
        float aM = (EPI == 3) ? alpha[0] : 0.f;
        #pragma unroll
        for (int i = 0; i < 64; i++) {
            int idx = tid + 128*i;
            int nl = idx >> 7, ml = idx & 127;
            size_t adr = ((size_t)(bb*DIM + col0 + nl))*HWSZ + hw0 + ml;
            if (EPI == 1) g_ssm[adr] = T[nl*129 + ml];
            else          Cout[adr] = g_xr[adr] + aM * T[nl*129 + ml];
        }
    }
}

// ---------------- launch ----------------
extern "C" void kernel_launch(void* const* d_in, const int* in_sizes, int n_in,
                              void* d_out, int out_size)
{
    const float* x        = (const float*)d_in[0];
    const float* ln1_g    = (const float*)d_in[1];
    const float* ln1_b    = (const float*)d_in[2];
    const float* ln2_g    = (const float*)d_in[3];
    const float* ln2_b    = (const float*)d_in[4];
    const float* dw_w     = (const float*)d_in[5];
    const float* bn_g     = (const float*)d_in[6];
    const float* bn_b     = (const float*)d_in[7];
    const float* bn_rm    = (const float*)d_in[8];
    const float* bn_rv    = (const float*)d_in[9];
    const float* ssm_ln_g = (const float*)d_in[10];
    const float* ssm_ln_b = (const float*)d_in[11];
    const float* xp_w     = (const float*)d_in[12];
    const float* xp_b     = (const float*)d_in[13];
    const float* dt_w     = (const float*)d_in[14];
    const float* dt_b     = (const float*)d_in[15];
    const float* A_log    = (const float*)d_in[16];
    const float* B_w      = (const float*)d_in[17];
    const float* C_w      = (const float*)d_in[18];
    const float* D_param  = (const float*)d_in[19];
    const float* out_w    = (const float*)d_in[20];
    const float* out_b    = (const float*)d_in[21];
    const float* mlp_w1   = (const float*)d_in[22];
    const float* mlp_b1   = (const float*)d_in[23];
    const float* mlp_w2   = (const float*)d_in[24];
    const float* mlp_b2   = (const float*)d_in[25];
    const float* aL       = (const float*)d_in[26];
    const float* aS       = (const float*)d_in[27];
    const float* aM       = (const float*)d_in[28];
    float* out = (float*)d_out;

    // allow >48KB dynamic smem for the GEMM kernels (immediate API, not captured)
    cudaFuncSetAttribute(k_mma<0,256,192>, cudaFuncAttributeMaxDynamicSharedMemorySize, SMEM_GEMM_BYTES);
    cudaFuncSetAttribute(k_mma<1,192,64>,  cudaFuncAttributeMaxDynamicSharedMemorySize, SMEM_GEMM_BYTES);
    cudaFuncSetAttribute(k_mma<2,HID,192>, cudaFuncAttributeMaxDynamicSharedMemorySize, SMEM_GEMM_BYTES);
    cudaFuncSetAttribute(k_mma<3,192,HID>, cudaFuncAttributeMaxDynamicSharedMemorySize, SMEM_GEMM_BYTES);

    // 1. prep
    k_prep<<<576, 256>>>(dt_w, B_w, C_w, xp_w, dt_b, xp_b, A_log, out_w, mlp_w1, mlp_w2);

    // 2. LN1 + ssm_ln (coalesced)
    k_ln<0><<<TOK/32, 1024>>>(x, ln1_g, ln1_b, ssm_ln_g, ssm_ln_b);

    // 3. projections
    k_mma<0, 256, 192><<<dim3(256/64, TOK/128), 128, SMEM_GEMM_BYTES>>>(nullptr, nullptr, nullptr, nullptr);

    // 4. scan: elementwise precompute + 3-pass chunked scan
    k_ssmpre<<<TOK*ST/256, 256>>>();
    k_scan1<<<NB*NCH, ST>>>();
    k_scan2<<<NB, ST>>>();
    k_scan3<<<NB*NCH, ST>>>();

    // 5. out projection + D*xn1 -> g_ssm (NCHW)
    k_mma<1, 192, 64><<<dim3(192/64, TOK/128), 128, SMEM_GEMM_BYTES>>>(out_b, nullptr, D_param, nullptr);

    // 6. conv + BN + residual combine -> g_xr (NCHW)
    k_combine<<<dim3(16, DIM, NB), 256>>>(x, dw_w, bn_g, bn_b, bn_rm, bn_rv, aL, aS);

    // 7. LN2
    k_ln<1><<<TOK/32, 1024>>>(nullptr, ln2_g, ln2_b, nullptr, nullptr);

    // 8. MLP fc1 + gelu
    k_mma<2, HID, 192><<<dim3(HID/64, TOK/128), 128, SMEM_GEMM_BYTES>>>(mlp_b1, nullptr, nullptr, nullptr);

    // 9. MLP fc2 + final residual -> d_out (NCHW)
    k_mma<3, 192, HID><<<dim3(192/64, TOK/128), 128, SMEM_GEMM_BYTES>>>(mlp_b2, out, nullptr, aM);
}

// round 6
// speedup vs baseline: 2.4955x; 1.0152x over previous
#include <cuda_runtime.h>
#include <math.h>
#include <stdint.h>

#define NB   8
#define DIM  192
#define ST   64
#define HWSZ 4096
#define TOK  (NB*HWSZ)
#define HID  768
#define CHL  32
#define NCH  (HWSZ/CHL)

// ---------------- scratch ----------------
__device__ float g_xn1[TOK*DIM];
__device__ float g_xn2[TOK*DIM];
__device__ float g_proj[TOK*256];
__device__ float g_Av[TOK*ST];
__device__ float g_h[TOK*ST];
__device__ float g_yh[TOK*ST];
__device__ float g_ssm[(size_t)TOK*DIM];
__device__ float g_xr[(size_t)TOK*DIM];
__device__ float g_xn3[TOK*DIM];
__device__ float g_hid[(size_t)TOK*HID];
__device__ float g_wcat[256*DIM];
__device__ float g_wout[DIM*ST];
__device__ float g_w1[HID*DIM];
__device__ float g_w2[DIM*HID];
__device__ float g_bias256[256];
__device__ float g_Aneg[ST];
__device__ float g_P[NB*NCH*ST];
__device__ float g_hend[NB*NCH*ST];
__device__ float g_hin[NB*NCH*ST];

// ---------------- helpers ----------------
__device__ __forceinline__ float tf32r(float x)
{ uint32_t u; asm("cvt.rna.tf32.f32 %0, %1;" : "=r"(u) : "f"(x)); return __uint_as_float(u); }

__device__ __forceinline__ void cp16(void* dst_smem, const void* src)
{
    uint32_t d = (uint32_t)__cvta_generic_to_shared(dst_smem);
    asm volatile("cp.async.cg.shared.global [%0], [%1], 16;" :: "r"(d), "l"(src));
}
__device__ __forceinline__ void cp_commit() { asm volatile("cp.async.commit_group;"); }
template<int W> __device__ __forceinline__ void cp_wait() { asm volatile("cp.async.wait_group %0;" :: "n"(W)); }

// ---------------- prep ----------------
__global__ void k_prep(const float* __restrict__ dt_w, const float* __restrict__ B_w,
                       const float* __restrict__ C_w,  const float* __restrict__ xp_w,
                       const float* __restrict__ dt_b, const float* __restrict__ xp_b,
                       const float* __restrict__ A_log, const float* __restrict__ out_w,
                       const float* __restrict__ mlp_w1, const float* __restrict__ mlp_w2)
{
    int i = blockIdx.x * blockDim.x + threadIdx.x;
    if (i < 256*DIM) {
        int n = i / DIM, k = i - n*DIM;
        float v;
        if      (n < 64)  v = dt_w[n*DIM + k];
        else if (n < 128) v = B_w[(n-64)*DIM + k];
        else if (n < 192) v = C_w[(n-128)*DIM + k];
        else              v = xp_w[(n-192)*DIM + k];
        g_wcat[i] = tf32r(v);
    }
    if (i < DIM*ST)  g_wout[i] = tf32r(out_w[i]);
    if (i < HID*DIM) { g_w1[i] = tf32r(mlp_w1[i]); g_w2[i] = tf32r(mlp_w2[i]); }
    if (i < 256) {
        float b = 0.f;
        if (i < 64)        b = dt_b[i];
        else if (i >= 192) b = xp_b[i-192];
        g_bias256[i] = b;
    }
    if (i < ST) g_Aneg[i] = -expf(A_log[i]);
}

// ---------------- LayerNorm (coalesced, 32 tok/block) ----------------
template<int MODE>
__global__ void __launch_bounds__(1024) k_ln(const float* __restrict__ xin,
                     const float* __restrict__ g1, const float* __restrict__ b1,
                     const float* __restrict__ g2, const float* __restrict__ b2)
{
    __shared__ float s[192*33];
    int tid = threadIdx.x;
    int tok0 = blockIdx.x * 32;
    int b = tok0 >> 12, hw0 = tok0 & (HWSZ-1);
    const float* src = (MODE == 0) ? xin : g_xr;
    #pragma unroll
    for (int i = 0; i < 6; i++) {
        int idx = tid + 1024*i;
        int c = idx >> 5, j = idx & 31;
        s[c*33 + j] = src[((size_t)(b*DIM + c))*HWSZ + hw0 + j];
    }
    __syncthreads();
    int w = tid >> 5, l = tid & 31;
    float v[6], sum = 0.f, sq = 0.f;
    #pragma unroll
    for (int i = 0; i < 6; i++) { v[i] = s[(l + 32*i)*33 + w]; sum += v[i]; sq += v[i]*v[i]; }
    #pragma unroll
    for (int o = 16; o > 0; o >>= 1) {
        sum += __shfl_xor_sync(0xffffffffu, sum, o);
        sq  += __shfl_xor_sync(0xffffffffu, sq,  o);
    }
    float mean = sum * (1.f/DIM), var = sq * (1.f/DIM) - mean*mean;
    float rs = rsqrtf(var + 1e-5f);
    float y[6];
    #pragma unroll
    for (int i = 0; i < 6; i++) { int c = l + 32*i; y[i] = (v[i] - mean) * rs * g1[c] + b1[c]; }
    __syncthreads();
    #pragma unroll
    for (int i = 0; i < 6; i++) s[(l + 32*i)*33 + w] = y[i];
    __syncthreads();
    {
        float* dst = (MODE == 0) ? g_xn1 : g_xn3;
        #pragma unroll
        for (int i = 0; i < 6; i++) {
            int idx = tid + 1024*i;
            int tok = idx / 192, c = idx - tok*192;
            float val = s[c*33 + tok];
            dst[(size_t)(tok0 + tok)*DIM + c] = (MODE == 0) ? val : tf32r(val);
        }
    }
    if (MODE == 0) {
        float s2a = 0.f, s2b = 0.f;
        #pragma unroll
        for (int i = 0; i < 6; i++) { s2a += y[i]; s2b += y[i]*y[i]; }
        #pragma unroll
        for (int o = 16; o > 0; o >>= 1) {
            s2a += __shfl_xor_sync(0xffffffffu, s2a, o);
            s2b += __shfl_xor_sync(0xffffffffu, s2b, o);
        }
        float m2 = s2a * (1.f/DIM), v2 = s2b * (1.f/DIM) - m2*m2;
        float rs2 = rsqrtf(v2 + 1e-5f);
        __syncthreads();
        #pragma unroll
        for (int i = 0; i < 6; i++) { int c = l + 32*i; s[(l + 32*i)*33 + w] = tf32r((y[i] - m2) * rs2 * g2[c] + b2[c]); }
        __syncthreads();
        #pragma unroll
        for (int i = 0; i < 6; i++) {
            int idx = tid + 1024*i;
            int tok = idx / 192, c = idx - tok*192;
            g_xn2[(size_t)(tok0 + tok)*DIM + c] = s[c*33 + tok];
        }
    }
}

// ---------------- scan pass 1: fused elementwise + local chunk scans ----------------
__global__ void k_scan1()
{
    int s = threadIdx.x, bidx = blockIdx.x;
    int b = bidx >> 7, ch = bidx & (NCH-1);
    float An = g_Aneg[s];
    float h = 0.f, P = 1.f;
    int tok0 = b*HWSZ + ch*CHL;
    bool c0 = (ch == 0);
    #pragma unroll 4
    for (int t = 0; t < CHL; t++) {
        const float* p = g_proj + (size_t)(tok0 + t)*256;
        float dt = p[s], Bv = p[64+s], xv = p[192+s];
        float sp = fmaxf(dt, 0.f) + log1pf(expf(-fabsf(dt)));
        float delta = sp * 0.01f + 1e-4f;
        float dA = fminf(fmaxf(delta * An, -10.f), -1e-4f);
        float Av = fminf(fmaxf(expf(dA), 0.001f), 0.999f);
        float BX = delta * Bv * xv;
        h = (c0 && t == 0) ? BX : Av*(h + BX);
        P *= Av;
        size_t o = (size_t)(tok0 + t)*ST + s;
        g_h[o] = h;
        g_Av[o] = Av;
    }
    g_P[bidx*ST + s] = P;
    g_hend[bidx*ST + s] = h;
}

// ---------------- scan pass 2: warp-parallel affine scan over chunk carries ----------------
// 512 chains (b,s), each a warp; NCH=128 chunks -> 4 per lane + 5-step shuffle scan.
__global__ void __launch_bounds__(256) k_scan2()
{
    int gw = blockIdx.x*8 + (threadIdx.x >> 5);   // 0..511
    int lane = threadIdx.x & 31;
    int b = gw >> 6, s = gw & 63;
    int base = (b*NCH)*ST + s;

    float P[4], E[4];
    #pragma unroll
    for (int j = 0; j < 4; j++) {
        int ch = lane*4 + j;
        P[j] = g_P[base + ch*ST];
        E[j] = g_hend[base + ch*ST];
    }
    // lane-local inclusive composition of its 4 chunks
    float tP = 1.f, tE = 0.f;
    #pragma unroll
    for (int j = 0; j < 4; j++) {
        float nP = P[j]*tP, nE = P[j]*tE + E[j];
        tP = nP; tE = nE;
    }
    // warp inclusive scan (affine compose: cur after prev)
    float sP = tP, sE = tE;
    #pragma unroll
    for (int off = 1; off < 32; off <<= 1) {
        float pP = __shfl_up_sync(0xffffffffu, sP, off);
        float pE = __shfl_up_sync(0xffffffffu, sE, off);
        if (lane >= off) { sE = sP*pE + sE; sP = sP*pP; }
    }
    // exclusive prefix for this lane
    float eP = __shfl_up_sync(0xffffffffu, sP, 1);
    float eE = __shfl_up_sync(0xffffffffu, sE, 1);
    if (lane == 0) { eP = 1.f; eE = 0.f; }
    // emit hin per chunk, composing forward
    float hP = eP, hE = eE;
    #pragma unroll
    for (int j = 0; j < 4; j++) {
        int ch = lane*4 + j;
        g_hin[base + ch*ST] = hE;
        float nP = P[j]*hP, nE = P[j]*hE + E[j];
        hP = nP; hE = nE;
    }
}

// ---------------- scan pass 3: fix-up + y = C*h ----------------
__global__ void k_scan3()
{
    int s = threadIdx.x, bidx = blockIdx.x;
    int b = bidx >> 7, ch = bidx & (NCH-1);
    float hin = g_hin[bidx*ST + s];
    float P = 1.f;
    int tok0 = b*HWSZ + ch*CHL;
    #pragma unroll 8
    for (int t = 0; t < CHL; t++) {
        size_t o = (size_t)(tok0 + t)*ST + s;
        P *= g_Av[o];
        float hf = g_h[o] + P*hin;
        g_yh[o] = tf32r(g_proj[(size_t)(tok0 + t)*256 + 128 + s] * hf);
    }
}

// ---------------- conv + BN + combine ----------------
__global__ void __launch_bounds__(256) k_combine(
    const float* __restrict__ x, const float* __restrict__ dw,
    const float* __restrict__ bn_g, const float* __restrict__ bn_b,
    const float* __restrict__ bn_rm, const float* __restrict__ bn_rv,
    const float* __restrict__ aL, const float* __restrict__ aS)
{
    int tid = threadIdx.x;
    int w = tid & 63, hs = tid >> 6;
    int h = blockIdx.x*4 + hs;
    int c = blockIdx.y, b = blockIdx.z;
    const float* xb = x + ((size_t)(b*DIM + c))*HWSZ;
    const float* wk = dw + c*9;
    float acc = 0.f;
    #pragma unroll
    for (int kh = 0; kh < 3; kh++) {
        int hh = h + kh - 1;
        if (hh < 0 || hh >= 64) continue;
        #pragma unroll
        for (int kw = 0; kw < 3; kw++) {
            int ww = w + kw - 1;
            if (ww < 0 || ww >= 64) continue;
            acc += xb[hh*64 + ww] * wk[kh*3 + kw];
        }
    }
    float scale = bn_g[c] * rsqrtf(bn_rv[c] + 1e-5f);
    float local = (acc - bn_rm[c]) * scale + bn_b[c];
    size_t base = ((size_t)(b*DIM + c))*HWSZ + h*64 + w;
    g_xr[base] = xb[h*64 + w] + aL[0]*local + aS[0]*g_ssm[base];
}

// ---------------- tf32 mma helper ----------------
__device__ __forceinline__ void mma_tf32(float* c, const uint32_t* a, const uint32_t* b)
{
    asm volatile("mma.sync.aligned.m16n8k8.row.col.f32.tf32.tf32.f32 "
        "{%0,%1,%2,%3}, {%4,%5,%6,%7}, {%8,%9}, {%0,%1,%2,%3};"
        : "+f"(c[0]), "+f"(c[1]), "+f"(c[2]), "+f"(c[3])
        : "r"(a[0]), "r"(a[1]), "r"(a[2]), "r"(a[3]), "r"(b[0]), "r"(b[1]));
}

// ---------------- TF32 GEMM: C[M,N] = A[M,K] @ Bw[N,K]^T ----------------
// BM=128, BK=32, BN templated (64/128/192). Warps: 4 in M x (BN/64) in N, tile 32x64.
// EPI 0: A=g_xn2, B=g_wcat -> g_proj                 (BN=128)
// EPI 1: A=g_yh,  B=g_wout + D*xn1 -> g_ssm (NCHW)   (BN=64)
// EPI 2: A=g_xn3, B=g_w1 + gelu -> g_hid             (BN=128)
// EPI 3: A=g_hid, B=g_w2; out = xr + aM*v (NCHW)     (BN=192)
template<int EPI, int N, int K, int BN>
__global__ void __launch_bounds__((BN/64)*128) k_mma(const float* __restrict__ bias,
                                                     const float* __restrict__ Dp,
                                                     const float* __restrict__ alpha,
                                                     float* __restrict__ Cout)
{
    constexpr int TPB = (BN/64)*128;
    extern __shared__ float sm[];
    const float* A  = (EPI == 0) ? g_xn2 : (EPI == 1) ? g_yh : (EPI == 2) ? g_xn3 : g_hid;
    const float* Bp = (EPI == 0) ? g_wcat : (EPI == 1) ? g_wout : (EPI == 2) ? g_w1 : g_w2;
    const float* bp = (EPI == 0) ? g_bias256 : bias;

    int tid = threadIdx.x;
    int wid = tid >> 5, lane = tid & 31;
    int wm = wid & 3, wn = wid >> 2;
    int g = lane >> 2, t4 = lane & 3;
    int row0 = blockIdx.y * 128, col0 = blockIdx.x * BN;
    int m0 = wm * 32, n0 = wn * 64;

    float acc[2][8][4];
    #pragma unroll
    for (int mi = 0; mi < 2; mi++)
        #pragma unroll
        for (int ni = 0; ni < 8; ni++)
            #pragma unroll
            for (int e = 0; e < 4; e++) acc[mi][ni][e] = 0.f;

    const int NK = K / 32;
    auto load_slab = [&](int kt, int st) {
        float* As = sm + st*(128*36);
        float* Bs = sm + 2*(128*36) + st*(BN*36);
        int k0 = kt * 32;
        for (int idx = tid; idx < 128*8; idx += TPB) {
            int m = idx >> 3, kq = idx & 7;
            cp16(&As[m*36 + kq*4], A + (size_t)(row0 + m)*K + k0 + kq*4);
        }
        for (int idx = tid; idx < BN*8; idx += TPB) {
            int n = idx >> 3, kq = idx & 7;
            cp16(&Bs[n*36 + kq*4], Bp + (size_t)(col0 + n)*K + k0 + kq*4);
        }
    };
    load_slab(0, 0);
    cp_commit();
    for (int kt = 0; kt < NK; kt++) {
        int cur = kt & 1;
        if (kt + 1 < NK) { load_slab(kt + 1, (kt + 1) & 1); cp_commit(); cp_wait<1>(); }
        else cp_wait<0>();
        __syncthreads();
        const uint32_t* As = reinterpret_cast<const uint32_t*>(sm + cur*(128*36));
        const uint32_t* Bs = reinterpret_cast<const uint32_t*>(sm + 2*(128*36) + cur*(BN*36));
        #pragma unroll
        for (int k8 = 0; k8 < 4; k8++) {
            int kb = k8 * 8;
            uint32_t a[2][4], b[8][2];
            #pragma unroll
            for (int mi = 0; mi < 2; mi++) {
                int r = m0 + mi*16 + g;
                a[mi][0] = As[r*36 + kb + t4];
                a[mi][1] = As[(r+8)*36 + kb + t4];
                a[mi][2] = As[r*36 + kb + t4 + 4];
                a[mi][3] = As[(r+8)*36 + kb + t4 + 4];
            }
            #pragma unroll
            for (int ni = 0; ni < 8; ni++) {
                int c = n0 + ni*8 + g;
                b[ni][0] = Bs[c*36 + kb + t4];
                b[ni][1] = Bs[c*36 + kb + t4 + 4];
            }
            #pragma unroll
            for (int mi = 0; mi < 2; mi++)
                #pragma unroll
                for (int ni = 0; ni < 8; ni++)
                    mma_tf32(acc[mi][ni], a[mi], b[ni]);
        }
        __syncthreads();
    }

    if (EPI == 0 || EPI == 2) {
        #pragma unroll
        for (int mi = 0; mi < 2; mi++)
            #pragma unroll
            for (int ni = 0; ni < 8; ni++)
                #pragma unroll
                for (int e = 0; e < 4; e++) {
                    int m = row0 + m0 + mi*16 + g + ((e >> 1) << 3);
                    int n = col0 + n0 + ni*8 + t4*2 + (e & 1);
                    float v = acc[mi][ni][e] + bp[n];
                    if (EPI == 2) {
                        v = 0.5f * v * (1.f + erff(v * 0.7071067811865476f));
                        g_hid[(size_t)m*N + n] = tf32r(v);
                    } else {
                        g_proj[(size_t)m*N + n] = v;
                    }
                }
    } else {
        float* T = sm;   // BN x 128, pitch 129
        __syncthreads();
        #pragma unroll
        for (int mi = 0; mi < 2; mi++)
            #pragma unroll
            for (int ni = 0; ni < 8; ni++)
                #pragma unroll
                for (int e = 0; e < 4; e++) {
                    int ml = m0 + mi*16 + g + ((e >> 1) << 3);
                    int nl = n0 + ni*8 + t4*2 + (e & 1);
                    int n = col0 + nl;
                    float v = acc[mi][ni][e] + bp[n];
                    if (EPI == 1) {
                        float d = fminf(fmaxf(Dp[n], -2.f), 2.f);
                        v += d * g_xn1[(size_t)(row0 + ml)*DIM + n];
                    }
                    T[nl*129 + ml] = v;
                }
        __syncthreads();
        int bb = row0 >> 12, hw0 = row0 & (HWSZ-1);
        float aM = (EPI == 3) ? alpha[0] : 0.f;
        for (int idx = tid; idx < BN*128; idx += TPB) {
            int nl = idx >> 7, ml = idx & 127;
            size_t adr = ((size_t)(bb*DIM + col0 + nl))*HWSZ + hw0 + ml;
            if (EPI == 1) g_ssm[adr] = T[nl*129 + ml];
            else          Cout[adr] = g_xr[adr] + aM * T[nl*129 + ml];
        }
    }
}

// smem bytes per instantiation
template<int BN, bool TRANS>
constexpr int smem_bytes()
{
    int main_b = (2*128*36 + 2*BN*36)*4;
    int t_b = TRANS ? BN*129*4 : 0;
    return main_b > t_b ? main_b : t_b;
}

// ---------------- launch ----------------
extern "C" void kernel_launch(void* const* d_in, const int* in_sizes, int n_in,
                              void* d_out, int out_size)
{
    const float* x        = (const float*)d_in[0];
    const float* ln1_g    = (const float*)d_in[1];
    const float* ln1_b    = (const float*)d_in[2];
    const float* ln2_g    = (const float*)d_in[3];
    const float* ln2_b    = (const float*)d_in[4];
    const float* dw_w     = (const float*)d_in[5];
    const float* bn_g     = (const float*)d_in[6];
    const float* bn_b     = (const float*)d_in[7];
    const float* bn_rm    = (const float*)d_in[8];
    const float* bn_rv    = (const float*)d_in[9];
    const float* ssm_ln_g = (const float*)d_in[10];
    const float* ssm_ln_b = (const float*)d_in[11];
    const float* xp_w     = (const float*)d_in[12];
    const float* xp_b     = (const float*)d_in[13];
    const float* dt_w     = (const float*)d_in[14];
    const float* dt_b     = (const float*)d_in[15];
    const float* A_log    = (const float*)d_in[16];
    const float* B_w      = (const float*)d_in[17];
    const float* C_w      = (const float*)d_in[18];
    const float* D_param  = (const float*)d_in[19];
    const float* out_w    = (const float*)d_in[20];
    const float* out_b    = (const float*)d_in[21];
    const float* mlp_w1   = (const float*)d_in[22];
    const float* mlp_b1   = (const float*)d_in[23];
    const float* mlp_w2   = (const float*)d_in[24];
    const float* mlp_b2   = (const float*)d_in[25];
    const float* aL       = (const float*)d_in[26];
    const float* aS       = (const float*)d_in[27];
    const float* aM       = (const float*)d_in[28];
    float* out = (float*)d_out;

    constexpr int SM0 = smem_bytes<128, false>();
    constexpr int SM1 = smem_bytes<64, true>();
    constexpr int SM2 = smem_bytes<128, false>();
    constexpr int SM3 = smem_bytes<192, true>();

    cudaFuncSetAttribute(k_mma<0,256,192,128>, cudaFuncAttributeMaxDynamicSharedMemorySize, SM0);
    cudaFuncSetAttribute(k_mma<1,192,64,64>,   cudaFuncAttributeMaxDynamicSharedMemorySize, SM1);
    cudaFuncSetAttribute(k_mma<2,HID,192,128>, cudaFuncAttributeMaxDynamicSharedMemorySize, SM2);
    cudaFuncSetAttribute(k_mma<3,192,HID,192>, cudaFuncAttributeMaxDynamicSharedMemorySize, SM3);

    k_prep<<<576, 256>>>(dt_w, B_w, C_w, xp_w, dt_b, xp_b, A_log, out_w, mlp_w1, mlp_w2);
    k_ln<0><<<TOK/32, 1024>>>(x, ln1_g, ln1_b, ssm_ln_g, ssm_ln_b);
    k_mma<0, 256, 192, 128><<<dim3(2, TOK/128), 256, SM0>>>(nullptr, nullptr, nullptr, nullptr);
    k_scan1<<<NB*NCH, ST>>>();
    k_scan2<<<64, 256>>>();
    k_scan3<<<NB*NCH, ST>>>();
    k_mma<1, 192, 64, 64><<<dim3(3, TOK/128), 128, SM1>>>(out_b, D_param, nullptr, nullptr);
    k_combine<<<dim3(16, DIM, NB), 256>>>(x, dw_w, bn_g, bn_b, bn_rm, bn_rv, aL, aS);
    k_ln<1><<<TOK/32, 1024>>>(nullptr, ln2_g, ln2_b, nullptr, nullptr);
    k_mma<2, HID, 192, 128><<<dim3(6, TOK/128), 256, SM2>>>(mlp_b1, nullptr, nullptr, nullptr);
    k_mma<3, 192, HID, 192><<<dim3(1, TOK/128), 384, SM3>>>(mlp_b2, nullptr, aM, out);
}

// round 7
// speedup vs baseline: 2.8815x; 1.1547x over previous
#include <cuda_runtime.h>
#include <cuda_fp16.h>
#include <math.h>
#include <stdint.h>

#define NB   8
#define DIM  192
#define ST   64
#define HWSZ 4096
#define TOK  (NB*HWSZ)
#define HID  768
#define CHL  32
#define NCH  (HWSZ/CHL)
#define PITCHH 40   // smem row pitch in halfs (80 bytes) -> conflict-free ldmatrix

// ---------------- scratch ----------------
__device__ float g_xn1[TOK*DIM];
__device__ __align__(16) __half g_xn2[TOK*DIM];
__device__ float g_proj[TOK*256];
__device__ float g_Av[TOK*ST];
__device__ float g_h[TOK*ST];
__device__ __align__(16) __half g_yh[TOK*ST];
__device__ float g_ssm[(size_t)TOK*DIM];
__device__ float g_xr[(size_t)TOK*DIM];
__device__ __align__(16) __half g_xn3[TOK*DIM];
__device__ __align__(16) __half g_hid[(size_t)TOK*HID];
__device__ __align__(16) __half g_wcat[256*DIM];
__device__ __align__(16) __half g_wout[DIM*ST];
__device__ __align__(16) __half g_w1[HID*DIM];
__device__ __align__(16) __half g_w2[DIM*HID];
__device__ float g_bias256[256];
__device__ float g_Aneg[ST];
__device__ float g_P[NB*NCH*ST];
__device__ float g_hend[NB*NCH*ST];
__device__ float g_hin[NB*NCH*ST];

// ---------------- helpers ----------------
__device__ __forceinline__ void cp16(void* dst_smem, const void* src)
{
    uint32_t d = (uint32_t)__cvta_generic_to_shared(dst_smem);
    asm volatile("cp.async.cg.shared.global [%0], [%1], 16;" :: "r"(d), "l"(src));
}
__device__ __forceinline__ void cp_commit() { asm volatile("cp.async.commit_group;"); }
template<int W> __device__ __forceinline__ void cp_wait() { asm volatile("cp.async.wait_group %0;" :: "n"(W)); }

__device__ __forceinline__ void ldm4(uint32_t* r, const void* smem)
{
    uint32_t a = (uint32_t)__cvta_generic_to_shared(smem);
    asm volatile("ldmatrix.sync.aligned.m8n8.x4.shared.b16 {%0,%1,%2,%3}, [%4];"
                 : "=r"(r[0]), "=r"(r[1]), "=r"(r[2]), "=r"(r[3]) : "r"(a));
}
__device__ __forceinline__ void mma_f16(float* c, const uint32_t* a, const uint32_t* b)
{
    asm volatile("mma.sync.aligned.m16n8k16.row.col.f32.f16.f16.f32 "
        "{%0,%1,%2,%3}, {%4,%5,%6,%7}, {%8,%9}, {%0,%1,%2,%3};"
        : "+f"(c[0]), "+f"(c[1]), "+f"(c[2]), "+f"(c[3])
        : "r"(a[0]), "r"(a[1]), "r"(a[2]), "r"(a[3]), "r"(b[0]), "r"(b[1]));
}

// ---------------- prep ----------------
__global__ void k_prep(const float* __restrict__ dt_w, const float* __restrict__ B_w,
                       const float* __restrict__ C_w,  const float* __restrict__ xp_w,
                       const float* __restrict__ dt_b, const float* __restrict__ xp_b,
                       const float* __restrict__ A_log, const float* __restrict__ out_w,
                       const float* __restrict__ mlp_w1, const float* __restrict__ mlp_w2)
{
    int i = blockIdx.x * blockDim.x + threadIdx.x;
    if (i < 256*DIM) {
        int n = i / DIM, k = i - n*DIM;
        float v;
        if      (n < 64)  v = dt_w[n*DIM + k];
        else if (n < 128) v = B_w[(n-64)*DIM + k];
        else if (n < 192) v = C_w[(n-128)*DIM + k];
        else              v = xp_w[(n-192)*DIM + k];
        g_wcat[i] = __float2half(v);
    }
    if (i < DIM*ST)  g_wout[i] = __float2half(out_w[i]);
    if (i < HID*DIM) { g_w1[i] = __float2half(mlp_w1[i]); g_w2[i] = __float2half(mlp_w2[i]); }
    if (i < 256) {
        float b = 0.f;
        if (i < 64)        b = dt_b[i];
        else if (i >= 192) b = xp_b[i-192];
        g_bias256[i] = b;
    }
    if (i < ST) g_Aneg[i] = -expf(A_log[i]);
}

// ---------------- LayerNorm (coalesced, 32 tok/block) ----------------
template<int MODE>
__global__ void __launch_bounds__(1024) k_ln(const float* __restrict__ xin,
                     const float* __restrict__ g1, const float* __restrict__ b1,
                     const float* __restrict__ g2, const float* __restrict__ b2)
{
    __shared__ float s[192*33];
    int tid = threadIdx.x;
    int tok0 = blockIdx.x * 32;
    int b = tok0 >> 12, hw0 = tok0 & (HWSZ-1);
    const float* src = (MODE == 0) ? xin : g_xr;
    #pragma unroll
    for (int i = 0; i < 6; i++) {
        int idx = tid + 1024*i;
        int c = idx >> 5, j = idx & 31;
        s[c*33 + j] = src[((size_t)(b*DIM + c))*HWSZ + hw0 + j];
    }
    __syncthreads();
    int w = tid >> 5, l = tid & 31;
    float v[6], sum = 0.f, sq = 0.f;
    #pragma unroll
    for (int i = 0; i < 6; i++) { v[i] = s[(l + 32*i)*33 + w]; sum += v[i]; sq += v[i]*v[i]; }
    #pragma unroll
    for (int o = 16; o > 0; o >>= 1) {
        sum += __shfl_xor_sync(0xffffffffu, sum, o);
        sq  += __shfl_xor_sync(0xffffffffu, sq,  o);
    }
    float mean = sum * (1.f/DIM), var = sq * (1.f/DIM) - mean*mean;
    float rs = rsqrtf(var + 1e-5f);
    float y[6];
    #pragma unroll
    for (int i = 0; i < 6; i++) { int c = l + 32*i; y[i] = (v[i] - mean) * rs * g1[c] + b1[c]; }
    __syncthreads();
    #pragma unroll
    for (int i = 0; i < 6; i++) s[(l + 32*i)*33 + w] = y[i];
    __syncthreads();
    #pragma unroll
    for (int i = 0; i < 6; i++) {
        int idx = tid + 1024*i;
        int tok = idx / 192, c = idx - tok*192;
        float val = s[c*33 + tok];
        if (MODE == 0) g_xn1[(size_t)(tok0 + tok)*DIM + c] = val;
        else           g_xn3[(size_t)(tok0 + tok)*DIM + c] = __float2half(val);
    }
    if (MODE == 0) {
        float s2a = 0.f, s2b = 0.f;
        #pragma unroll
        for (int i = 0; i < 6; i++) { s2a += y[i]; s2b += y[i]*y[i]; }
        #pragma unroll
        for (int o = 16; o > 0; o >>= 1) {
            s2a += __shfl_xor_sync(0xffffffffu, s2a, o);
            s2b += __shfl_xor_sync(0xffffffffu, s2b, o);
        }
        float m2 = s2a * (1.f/DIM), v2 = s2b * (1.f/DIM) - m2*m2;
        float rs2 = rsqrtf(v2 + 1e-5f);
        __syncthreads();
        #pragma unroll
        for (int i = 0; i < 6; i++) { int c = l + 32*i; s[(l + 32*i)*33 + w] = (y[i] - m2) * rs2 * g2[c] + b2[c]; }
        __syncthreads();
        #pragma unroll
        for (int i = 0; i < 6; i++) {
            int idx = tid + 1024*i;
            int tok = idx / 192, c = idx - tok*192;
            g_xn2[(size_t)(tok0 + tok)*DIM + c] = __float2half(s[c*33 + tok]);
        }
    }
}

// ---------------- scan pass 1: fused elementwise + local chunk scans ----------------
__global__ void k_scan1()
{
    int s = threadIdx.x, bidx = blockIdx.x;
    int b = bidx >> 7, ch = bidx & (NCH-1);
    float An = g_Aneg[s];
    float h = 0.f, P = 1.f;
    int tok0 = b*HWSZ + ch*CHL;
    bool c0 = (ch == 0);
    #pragma unroll 4
    for (int t = 0; t < CHL; t++) {
        const float* p = g_proj + (size_t)(tok0 + t)*256;
        float dt = p[s], Bv = p[64+s], xv = p[192+s];
        float sp = fmaxf(dt, 0.f) + log1pf(expf(-fabsf(dt)));
        float delta = sp * 0.01f + 1e-4f;
        float dA = fminf(fmaxf(delta * An, -10.f), -1e-4f);
        float Av = fminf(fmaxf(expf(dA), 0.001f), 0.999f);
        float BX = delta * Bv * xv;
        h = (c0 && t == 0) ? BX : Av*(h + BX);
        P *= Av;
        size_t o = (size_t)(tok0 + t)*ST + s;
        g_h[o] = h;
        g_Av[o] = Av;
    }
    g_P[bidx*ST + s] = P;
    g_hend[bidx*ST + s] = h;
}

// ---------------- scan pass 2: warp-parallel affine scan over chunk carries ----------------
__global__ void __launch_bounds__(256) k_scan2()
{
    int gw = blockIdx.x*8 + (threadIdx.x >> 5);
    int lane = threadIdx.x & 31;
    int b = gw >> 6, s = gw & 63;
    int base = (b*NCH)*ST + s;

    float P[4], E[4];
    #pragma unroll
    for (int j = 0; j < 4; j++) {
        int ch = lane*4 + j;
        P[j] = g_P[base + ch*ST];
        E[j] = g_hend[base + ch*ST];
    }
    float tP = 1.f, tE = 0.f;
    #pragma unroll
    for (int j = 0; j < 4; j++) { float nP = P[j]*tP, nE = P[j]*tE + E[j]; tP = nP; tE = nE; }
    float sP = tP, sE = tE;
    #pragma unroll
    for (int off = 1; off < 32; off <<= 1) {
        float pP = __shfl_up_sync(0xffffffffu, sP, off);
        float pE = __shfl_up_sync(0xffffffffu, sE, off);
        if (lane >= off) { sE = sP*pE + sE; sP = sP*pP; }
    }
    float eP = __shfl_up_sync(0xffffffffu, sP, 1);
    float eE = __shfl_up_sync(0xffffffffu, sE, 1);
    if (lane == 0) { eP = 1.f; eE = 0.f; }
    float hP = eP, hE = eE;
    #pragma unroll
    for (int j = 0; j < 4; j++) {
        int ch = lane*4 + j;
        g_hin[base + ch*ST] = hE;
        float nP = P[j]*hP, nE = P[j]*hE + E[j];
        hP = nP; hE = nE;
    }
}

// ---------------- scan pass 3: fix-up + y = C*h (half) ----------------
__global__ void k_scan3()
{
    int s = threadIdx.x, bidx = blockIdx.x;
    int b = bidx >> 7, ch = bidx & (NCH-1);
    float hin = g_hin[bidx*ST + s];
    float P = 1.f;
    int tok0 = b*HWSZ + ch*CHL;
    #pragma unroll 8
    for (int t = 0; t < CHL; t++) {
        size_t o = (size_t)(tok0 + t)*ST + s;
        P *= g_Av[o];
        float hf = g_h[o] + P*hin;
        g_yh[o] = __float2half(g_proj[(size_t)(tok0 + t)*256 + 128 + s] * hf);
    }
}

// ---------------- conv + BN + combine ----------------
__global__ void __launch_bounds__(256) k_combine(
    const float* __restrict__ x, const float* __restrict__ dw,
    const float* __restrict__ bn_g, const float* __restrict__ bn_b,
    const float* __restrict__ bn_rm, const float* __restrict__ bn_rv,
    const float* __restrict__ aL, const float* __restrict__ aS)
{
    int tid = threadIdx.x;
    int w = tid & 63, hs = tid >> 6;
    int h = blockIdx.x*4 + hs;
    int c = blockIdx.y, b = blockIdx.z;
    const float* xb = x + ((size_t)(b*DIM + c))*HWSZ;
    const float* wk = dw + c*9;
    float acc = 0.f;
    #pragma unroll
    for (int kh = 0; kh < 3; kh++) {
        int hh = h + kh - 1;
        if (hh < 0 || hh >= 64) continue;
        #pragma unroll
        for (int kw = 0; kw < 3; kw++) {
            int ww = w + kw - 1;
            if (ww < 0 || ww >= 64) continue;
            acc += xb[hh*64 + ww] * wk[kh*3 + kw];
        }
    }
    float scale = bn_g[c] * rsqrtf(bn_rv[c] + 1e-5f);
    float local = (acc - bn_rm[c]) * scale + bn_b[c];
    size_t base = ((size_t)(b*DIM + c))*HWSZ + h*64 + w;
    g_xr[base] = xb[h*64 + w] + aL[0]*local + aS[0]*g_ssm[base];
}

// ---------------- FP16 tensor-core GEMM (ldmatrix + m16n8k16) ----------------
// C[M,N] = A[M,K] @ Bw[N,K]^T. BM=128, BK=32, BN in {64,128,192}; warp tile 32x64.
// EPI 0: A=g_xn2, B=g_wcat -> g_proj (float)
// EPI 1: A=g_yh,  B=g_wout + D*xn1 -> g_ssm (NCHW float)
// EPI 2: A=g_xn3, B=g_w1 + gelu -> g_hid (half)
// EPI 3: A=g_hid, B=g_w2; out = xr + aM*v -> d_out (NCHW float)
template<int EPI, int N, int K, int BN>
__global__ void __launch_bounds__((BN/64)*128) k_mma(const float* __restrict__ bias,
                                                     const float* __restrict__ Dp,
                                                     const float* __restrict__ alpha,
                                                     float* __restrict__ Cout)
{
    constexpr int TPB = (BN/64)*128;
    extern __shared__ char smc[];
    __half* Asm = reinterpret_cast<__half*>(smc);                       // 2 x 128*PITCHH
    __half* Bsm = reinterpret_cast<__half*>(smc) + 2*128*PITCHH;        // 2 x BN*PITCHH
    const __half* A  = (EPI == 0) ? g_xn2 : (EPI == 1) ? g_yh : (EPI == 2) ? g_xn3 : g_hid;
    const __half* Bp = (EPI == 0) ? g_wcat : (EPI == 1) ? g_wout : (EPI == 2) ? g_w1 : g_w2;
    const float* bp = (EPI == 0) ? g_bias256 : bias;

    int tid = threadIdx.x;
    int wid = tid >> 5, lane = tid & 31;
    int wm = wid & 3, wn = wid >> 2;
    int g = lane >> 2, t4 = lane & 3;
    int row0 = blockIdx.y * 128, col0 = blockIdx.x * BN;
    int m0 = wm * 32, n0 = wn * 64;
    int lrow = lane & 7, lmat = lane >> 3;
    int a_moff = (lmat & 1)*8, a_koff = (lmat >> 1)*8;
    int b_noff = (lmat >> 1)*8, b_koff = (lmat & 1)*8;

    float acc[2][8][4];
    #pragma unroll
    for (int mi = 0; mi < 2; mi++)
        #pragma unroll
        for (int ni = 0; ni < 8; ni++)
            #pragma unroll
            for (int e = 0; e < 4; e++) acc[mi][ni][e] = 0.f;

    const int NK = K / 32;
    auto load_slab = [&](int kt, int st) {
        __half* As = Asm + st*128*PITCHH;
        __half* Bs = Bsm + st*BN*PITCHH;
        int k0 = kt * 32;
        for (int idx = tid; idx < 128*4; idx += TPB) {
            int m = idx >> 2, c = idx & 3;
            cp16(As + m*PITCHH + c*8, A + (size_t)(row0 + m)*K + k0 + c*8);
        }
        for (int idx = tid; idx < BN*4; idx += TPB) {
            int n = idx >> 2, c = idx & 3;
            cp16(Bs + n*PITCHH + c*8, Bp + (size_t)(col0 + n)*K + k0 + c*8);
        }
    };
    load_slab(0, 0);
    cp_commit();
    for (int kt = 0; kt < NK; kt++) {
        int cur = kt & 1;
        if (kt + 1 < NK) { load_slab(kt + 1, (kt + 1) & 1); cp_commit(); cp_wait<1>(); }
        else cp_wait<0>();
        __syncthreads();
        const __half* As = Asm + cur*128*PITCHH;
        const __half* Bs = Bsm + cur*BN*PITCHH;
        #pragma unroll
        for (int ks = 0; ks < 2; ks++) {
            int kb = ks*16;
            uint32_t a[2][4], b[4][4];
            #pragma unroll
            for (int mi = 0; mi < 2; mi++)
                ldm4(a[mi], As + (m0 + mi*16 + lrow + a_moff)*PITCHH + kb + a_koff);
            #pragma unroll
            for (int nb = 0; nb < 4; nb++)
                ldm4(b[nb], Bs + (n0 + nb*16 + lrow + b_noff)*PITCHH + kb + b_koff);
            #pragma unroll
            for (int mi = 0; mi < 2; mi++)
                #pragma unroll
                for (int ni = 0; ni < 8; ni++)
                    mma_f16(acc[mi][ni], a[mi], &b[ni >> 1][(ni & 1)*2]);
        }
        __syncthreads();
    }

    if (EPI == 0 || EPI == 2) {
        #pragma unroll
        for (int mi = 0; mi < 2; mi++)
            #pragma unroll
            for (int ni = 0; ni < 8; ni++)
                #pragma unroll
                for (int e = 0; e < 4; e++) {
                    int m = row0 + m0 + mi*16 + g + ((e >> 1) << 3);
                    int n = col0 + n0 + ni*8 + t4*2 + (e & 1);
                    float v = acc[mi][ni][e] + bp[n];
                    if (EPI == 2) {
                        v = 0.5f * v * (1.f + erff(v * 0.7071067811865476f));
                        g_hid[(size_t)m*N + n] = __float2half(v);
                    } else {
                        g_proj[(size_t)m*N + n] = v;
                    }
                }
    } else {
        float* T = reinterpret_cast<float*>(smc);   // BN x 128, pitch 129
        __syncthreads();
        #pragma unroll
        for (int mi = 0; mi < 2; mi++)
            #pragma unroll
            for (int ni = 0; ni < 8; ni++)
                #pragma unroll
                for (int e = 0; e < 4; e++) {
                    int ml = m0 + mi*16 + g + ((e >> 1) << 3);
                    int nl = n0 + ni*8 + t4*2 + (e & 1);
                    int n = col0 + nl;
                    float v = acc[mi][ni][e] + bp[n];
                    if (EPI == 1) {
                        float d = fminf(fmaxf(Dp[n], -2.f), 2.f);
                        v += d * g_xn1[(size_t)(row0 + ml)*DIM + n];
                    }
                    T[nl*129 + ml] = v;
                }
        __syncthreads();
        int bb = row0 >> 12, hw0 = row0 & (HWSZ-1);
        float aM = (EPI == 3) ? alpha[0] : 0.f;
        for (int idx = tid; idx < BN*128; idx += TPB) {
            int nl = idx >> 7, ml = idx & 127;
            size_t adr = ((size_t)(bb*DIM + col0 + nl))*HWSZ + hw0 + ml;
            if (EPI == 1) g_ssm[adr] = T[nl*129 + ml];
            else          Cout[adr] = g_xr[adr] + aM * T[nl*129 + ml];
        }
    }
}

template<int BN, bool TRANS>
constexpr int smem_bytes()
{
    int main_b = (2*128*PITCHH + 2*BN*PITCHH)*2;
    int t_b = TRANS ? BN*129*4 : 0;
    return main_b > t_b ? main_b : t_b;
}

// ---------------- launch ----------------
extern "C" void kernel_launch(void* const* d_in, const int* in_sizes, int n_in,
                              void* d_out, int out_size)
{
    const float* x        = (const float*)d_in[0];
    const float* ln1_g    = (const float*)d_in[1];
    const float* ln1_b    = (const float*)d_in[2];
    const float* ln2_g    = (const float*)d_in[3];
    const float* ln2_b    = (const float*)d_in[4];
    const float* dw_w     = (const float*)d_in[5];
    const float* bn_g     = (const float*)d_in[6];
    const float* bn_b     = (const float*)d_in[7];
    const float* bn_rm    = (const float*)d_in[8];
    const float* bn_rv    = (const float*)d_in[9];
    const float* ssm_ln_g = (const float*)d_in[10];
    const float* ssm_ln_b = (const float*)d_in[11];
    const float* xp_w     = (const float*)d_in[12];
    const float* xp_b     = (const float*)d_in[13];
    const float* dt_w     = (const float*)d_in[14];
    const float* dt_b     = (const float*)d_in[15];
    const float* A_log    = (const float*)d_in[16];
    const float* B_w      = (const float*)d_in[17];
    const float* C_w      = (const float*)d_in[18];
    const float* D_param  = (const float*)d_in[19];
    const float* out_w    = (const float*)d_in[20];
    const float* out_b    = (const float*)d_in[21];
    const float* mlp_w1   = (const float*)d_in[22];
    const float* mlp_b1   = (const float*)d_in[23];
    const float* mlp_w2   = (const float*)d_in[24];
    const float* mlp_b2   = (const float*)d_in[25];
    const float* aL       = (const float*)d_in[26];
    const float* aS       = (const float*)d_in[27];
    const float* aM       = (const float*)d_in[28];
    float* out = (float*)d_out;

    constexpr int SM0 = smem_bytes<128, false>();
    constexpr int SM1 = smem_bytes<64, true>();
    constexpr int SM2 = smem_bytes<128, false>();
    constexpr int SM3 = smem_bytes<192, true>();

    cudaFuncSetAttribute(k_mma<0,256,192,128>, cudaFuncAttributeMaxDynamicSharedMemorySize, SM0);
    cudaFuncSetAttribute(k_mma<1,192,64,64>,   cudaFuncAttributeMaxDynamicSharedMemorySize, SM1);
    cudaFuncSetAttribute(k_mma<2,HID,192,128>, cudaFuncAttributeMaxDynamicSharedMemorySize, SM2);
    cudaFuncSetAttribute(k_mma<3,192,HID,192>, cudaFuncAttributeMaxDynamicSharedMemorySize, SM3);

    k_prep<<<576, 256>>>(dt_w, B_w, C_w, xp_w, dt_b, xp_b, A_log, out_w, mlp_w1, mlp_w2);
    k_ln<0><<<TOK/32, 1024>>>(x, ln1_g, ln1_b, ssm_ln_g, ssm_ln_b);
    k_mma<0, 256, 192, 128><<<dim3(2, TOK/128), 256, SM0>>>(nullptr, nullptr, nullptr, nullptr);
    k_scan1<<<NB*NCH, ST>>>();
    k_scan2<<<64, 256>>>();
    k_scan3<<<NB*NCH, ST>>>();
    k_mma<1, 192, 64, 64><<<dim3(3, TOK/128), 128, SM1>>>(out_b, D_param, nullptr, nullptr);
    k_combine<<<dim3(16, DIM, NB), 256>>>(x, dw_w, bn_g, bn_b, bn_rm, bn_rv, aL, aS);
    k_ln<1><<<TOK/32, 1024>>>(nullptr, ln2_g, ln2_b, nullptr, nullptr);
    k_mma<2, HID, 192, 128><<<dim3(6, TOK/128), 256, SM2>>>(mlp_b1, nullptr, nullptr, nullptr);
    k_mma<3, 192, HID, 192><<<dim3(1, TOK/128), 384, SM3>>>(mlp_b2, nullptr, aM, out);
}

// round 8
// speedup vs baseline: 3.2051x; 1.1123x over previous
#include <cuda_runtime.h>
#include <cuda_fp16.h>
#include <math.h>
#include <stdint.h>

#define NB   8
#define DIM  192
#define ST   64
#define HWSZ 4096
#define TOK  (NB*HWSZ)
#define HID  768
#define CHL  16
#define NCH  (HWSZ/CHL)     // 256
#define PITCHH 72           // smem row pitch in halfs (144B) -> conflict-free ldmatrix

// ---------------- scratch ----------------
__device__ float g_xn1[TOK*DIM];
__device__ __align__(16) __half g_xn2[TOK*DIM];
__device__ float g_proj[TOK*256];
__device__ float g_Av[TOK*ST];
__device__ float g_h[TOK*ST];
__device__ __align__(16) __half g_yh[TOK*ST];
__device__ float g_ssm[(size_t)TOK*DIM];
__device__ float g_xr[(size_t)TOK*DIM];
__device__ __align__(16) __half g_xn3[TOK*DIM];
__device__ __align__(16) __half g_hid[(size_t)TOK*HID];
__device__ __align__(16) __half g_wcat[256*DIM];
__device__ __align__(16) __half g_wout[DIM*ST];
__device__ __align__(16) __half g_w1[HID*DIM];
__device__ __align__(16) __half g_w2[DIM*HID];
__device__ float g_bias256[256];
__device__ float g_Aneg[ST];
__device__ float g_P[NB*NCH*ST];
__device__ float g_hend[NB*NCH*ST];
__device__ float g_hin[NB*NCH*ST];

// ---------------- helpers ----------------
__device__ __forceinline__ void cp16(void* dst_smem, const void* src)
{
    uint32_t d = (uint32_t)__cvta_generic_to_shared(dst_smem);
    asm volatile("cp.async.cg.shared.global [%0], [%1], 16;" :: "r"(d), "l"(src));
}
__device__ __forceinline__ void cp_commit() { asm volatile("cp.async.commit_group;"); }
template<int W> __device__ __forceinline__ void cp_wait() { asm volatile("cp.async.wait_group %0;" :: "n"(W)); }

__device__ __forceinline__ void ldm4(uint32_t* r, const void* smem)
{
    uint32_t a = (uint32_t)__cvta_generic_to_shared(smem);
    asm volatile("ldmatrix.sync.aligned.m8n8.x4.shared.b16 {%0,%1,%2,%3}, [%4];"
                 : "=r"(r[0]), "=r"(r[1]), "=r"(r[2]), "=r"(r[3]) : "r"(a));
}
__device__ __forceinline__ void mma_f16(float* c, const uint32_t* a, const uint32_t* b)
{
    asm volatile("mma.sync.aligned.m16n8k16.row.col.f32.f16.f16.f32 "
        "{%0,%1,%2,%3}, {%4,%5,%6,%7}, {%8,%9}, {%0,%1,%2,%3};"
        : "+f"(c[0]), "+f"(c[1]), "+f"(c[2]), "+f"(c[3])
        : "r"(a[0]), "r"(a[1]), "r"(a[2]), "r"(a[3]), "r"(b[0]), "r"(b[1]));
}

// ---------------- prep ----------------
__global__ void k_prep(const float* __restrict__ dt_w, const float* __restrict__ B_w,
                       const float* __restrict__ C_w,  const float* __restrict__ xp_w,
                       const float* __restrict__ dt_b, const float* __restrict__ xp_b,
                       const float* __restrict__ A_log, const float* __restrict__ out_w,
                       const float* __restrict__ mlp_w1, const float* __restrict__ mlp_w2)
{
    int i = blockIdx.x * blockDim.x + threadIdx.x;
    if (i < 256*DIM) {
        int n = i / DIM, k = i - n*DIM;
        float v;
        if      (n < 64)  v = dt_w[n*DIM + k];
        else if (n < 128) v = B_w[(n-64)*DIM + k];
        else if (n < 192) v = C_w[(n-128)*DIM + k];
        else              v = xp_w[(n-192)*DIM + k];
        g_wcat[i] = __float2half(v);
    }
    if (i < DIM*ST)  g_wout[i] = __float2half(out_w[i]);
    if (i < HID*DIM) { g_w1[i] = __float2half(mlp_w1[i]); g_w2[i] = __float2half(mlp_w2[i]); }
    if (i < 256) {
        float b = 0.f;
        if (i < 64)        b = dt_b[i];
        else if (i >= 192) b = xp_b[i-192];
        g_bias256[i] = b;
    }
    if (i < ST) g_Aneg[i] = -expf(A_log[i]);
}

// ---------------- LayerNorm (coalesced, 32 tok/block) ----------------
template<int MODE>
__global__ void __launch_bounds__(1024) k_ln(const float* __restrict__ xin,
                     const float* __restrict__ g1, const float* __restrict__ b1,
                     const float* __restrict__ g2, const float* __restrict__ b2)
{
    __shared__ float s[192*33];
    int tid = threadIdx.x;
    int tok0 = blockIdx.x * 32;
    int b = tok0 >> 12, hw0 = tok0 & (HWSZ-1);
    const float* src = (MODE == 0) ? xin : g_xr;
    #pragma unroll
    for (int i = 0; i < 6; i++) {
        int idx = tid + 1024*i;
        int c = idx >> 5, j = idx & 31;
        s[c*33 + j] = src[((size_t)(b*DIM + c))*HWSZ + hw0 + j];
    }
    __syncthreads();
    int w = tid >> 5, l = tid & 31;
    float v[6], sum = 0.f, sq = 0.f;
    #pragma unroll
    for (int i = 0; i < 6; i++) { v[i] = s[(l + 32*i)*33 + w]; sum += v[i]; sq += v[i]*v[i]; }
    #pragma unroll
    for (int o = 16; o > 0; o >>= 1) {
        sum += __shfl_xor_sync(0xffffffffu, sum, o);
        sq  += __shfl_xor_sync(0xffffffffu, sq,  o);
    }
    float mean = sum * (1.f/DIM), var = sq * (1.f/DIM) - mean*mean;
    float rs = rsqrtf(var + 1e-5f);
    float y[6];
    #pragma unroll
    for (int i = 0; i < 6; i++) { int c = l + 32*i; y[i] = (v[i] - mean) * rs * g1[c] + b1[c]; }
    __syncthreads();
    #pragma unroll
    for (int i = 0; i < 6; i++) s[(l + 32*i)*33 + w] = y[i];
    __syncthreads();
    #pragma unroll
    for (int i = 0; i < 6; i++) {
        int idx = tid + 1024*i;
        int tok = idx / 192, c = idx - tok*192;
        float val = s[c*33 + tok];
        if (MODE == 0) g_xn1[(size_t)(tok0 + tok)*DIM + c] = val;
        else           g_xn3[(size_t)(tok0 + tok)*DIM + c] = __float2half(val);
    }
    if (MODE == 0) {
        float s2a = 0.f, s2b = 0.f;
        #pragma unroll
        for (int i = 0; i < 6; i++) { s2a += y[i]; s2b += y[i]*y[i]; }
        #pragma unroll
        for (int o = 16; o > 0; o >>= 1) {
            s2a += __shfl_xor_sync(0xffffffffu, s2a, o);
            s2b += __shfl_xor_sync(0xffffffffu, s2b, o);
        }
        float m2 = s2a * (1.f/DIM), v2 = s2b * (1.f/DIM) - m2*m2;
        float rs2 = rsqrtf(v2 + 1e-5f);
        __syncthreads();
        #pragma unroll
        for (int i = 0; i < 6; i++) { int c = l + 32*i; s[(l + 32*i)*33 + w] = (y[i] - m2) * rs2 * g2[c] + b2[c]; }
        __syncthreads();
        #pragma unroll
        for (int i = 0; i < 6; i++) {
            int idx = tid + 1024*i;
            int tok = idx / 192, c = idx - tok*192;
            g_xn2[(size_t)(tok0 + tok)*DIM + c] = __float2half(s[c*33 + tok]);
        }
    }
}

// ---------------- scan pass 1: fused elementwise + local chunk scans ----------------
__global__ void k_scan1()
{
    int s = threadIdx.x, bidx = blockIdx.x;
    int b = bidx >> 8, ch = bidx & (NCH-1);
    float An = g_Aneg[s];
    float h = 0.f, P = 1.f;
    int tok0 = b*HWSZ + ch*CHL;
    bool c0 = (ch == 0);
    #pragma unroll 4
    for (int t = 0; t < CHL; t++) {
        const float* p = g_proj + (size_t)(tok0 + t)*256;
        float dt = p[s], Bv = p[64+s], xv = p[192+s];
        float sp = fmaxf(dt, 0.f) + log1pf(expf(-fabsf(dt)));
        float delta = sp * 0.01f + 1e-4f;
        float dA = fminf(fmaxf(delta * An, -10.f), -1e-4f);
        float Av = fminf(fmaxf(expf(dA), 0.001f), 0.999f);
        float BX = delta * Bv * xv;
        h = (c0 && t == 0) ? BX : Av*(h + BX);
        P *= Av;
        size_t o = (size_t)(tok0 + t)*ST + s;
        g_h[o] = h;
        g_Av[o] = Av;
    }
    g_P[bidx*ST + s] = P;
    g_hend[bidx*ST + s] = h;
}

// ---------------- scan pass 2: warp-parallel affine scan over chunk carries ----------------
// 512 chains (b,s), one warp each; NCH=256 chunks -> 8 per lane + 5-step shuffle scan.
__global__ void __launch_bounds__(256) k_scan2()
{
    int gw = blockIdx.x*8 + (threadIdx.x >> 5);
    int lane = threadIdx.x & 31;
    int b = gw >> 6, s = gw & 63;
    int base = (b*NCH)*ST + s;

    float P[8], E[8];
    #pragma unroll
    for (int j = 0; j < 8; j++) {
        int ch = lane*8 + j;
        P[j] = g_P[base + ch*ST];
        E[j] = g_hend[base + ch*ST];
    }
    float tP = 1.f, tE = 0.f;
    #pragma unroll
    for (int j = 0; j < 8; j++) { float nP = P[j]*tP, nE = P[j]*tE + E[j]; tP = nP; tE = nE; }
    float sP = tP, sE = tE;
    #pragma unroll
    for (int off = 1; off < 32; off <<= 1) {
        float pP = __shfl_up_sync(0xffffffffu, sP, off);
        float pE = __shfl_up_sync(0xffffffffu, sE, off);
        if (lane >= off) { sE = sP*pE + sE; sP = sP*pP; }
    }
    float eP = __shfl_up_sync(0xffffffffu, sP, 1);
    float eE = __shfl_up_sync(0xffffffffu, sE, 1);
    if (lane == 0) { eP = 1.f; eE = 0.f; }
    float hP = eP, hE = eE;
    #pragma unroll
    for (int j = 0; j < 8; j++) {
        int ch = lane*8 + j;
        g_hin[base + ch*ST] = hE;
        float nP = P[j]*hP, nE = P[j]*hE + E[j];
        hP = nP; hE = nE;
    }
}

// ---------------- scan pass 3: fix-up + y = C*h (half) ----------------
__global__ void k_scan3()
{
    int s = threadIdx.x, bidx = blockIdx.x;
    int b = bidx >> 8, ch = bidx & (NCH-1);
    float hin = g_hin[bidx*ST + s];
    float P = 1.f;
    int tok0 = b*HWSZ + ch*CHL;
    #pragma unroll 4
    for (int t = 0; t < CHL; t++) {
        size_t o = (size_t)(tok0 + t)*ST + s;
        P *= g_Av[o];
        float hf = g_h[o] + P*hin;
        g_yh[o] = __float2half(g_proj[(size_t)(tok0 + t)*256 + 128 + s] * hf);
    }
}

// ---------------- conv + BN + combine ----------------
__global__ void __launch_bounds__(256) k_combine(
    const float* __restrict__ x, const float* __restrict__ dw,
    const float* __restrict__ bn_g, const float* __restrict__ bn_b,
    const float* __restrict__ bn_rm, const float* __restrict__ bn_rv,
    const float* __restrict__ aL, const float* __restrict__ aS)
{
    int tid = threadIdx.x;
    int w = tid & 63, hs = tid >> 6;
    int h = blockIdx.x*4 + hs;
    int c = blockIdx.y, b = blockIdx.z;
    const float* xb = x + ((size_t)(b*DIM + c))*HWSZ;
    const float* wk = dw + c*9;
    float acc = 0.f;
    #pragma unroll
    for (int kh = 0; kh < 3; kh++) {
        int hh = h + kh - 1;
        if (hh < 0 || hh >= 64) continue;
        #pragma unroll
        for (int kw = 0; kw < 3; kw++) {
            int ww = w + kw - 1;
            if (ww < 0 || ww >= 64) continue;
            acc += xb[hh*64 + ww] * wk[kh*3 + kw];
        }
    }
    float scale = bn_g[c] * rsqrtf(bn_rv[c] + 1e-5f);
    float local = (acc - bn_rm[c]) * scale + bn_b[c];
    size_t base = ((size_t)(b*DIM + c))*HWSZ + h*64 + w;
    g_xr[base] = xb[h*64 + w] + aL[0]*local + aS[0]*g_ssm[base];
}

// ---------------- FP16 tensor-core GEMM (ldmatrix + m16n8k16, BK=64) ----------------
// C[M,N] = A[M,K] @ Bw[N,K]^T. BM=128, BN=64, BK=64; 4 warps, warp tile 32x64.
// EPI 0: A=g_xn2, B=g_wcat -> g_proj (float)
// EPI 1: A=g_yh,  B=g_wout + D*xn1 -> g_ssm (NCHW float)
// EPI 2: A=g_xn3, B=g_w1 + gelu -> g_hid (half)
// EPI 3: A=g_hid, B=g_w2; out = xr + aM*v -> d_out (NCHW float)
#define STAGEH ((128 + 64) * PITCHH)     // halfs per stage
template<int EPI, int N, int K>
__global__ void __launch_bounds__(128) k_mma(const float* __restrict__ bias,
                                             const float* __restrict__ Dp,
                                             const float* __restrict__ alpha,
                                             float* __restrict__ Cout)
{
    extern __shared__ char smc[];
    __half* stage0 = reinterpret_cast<__half*>(smc);
    const __half* A  = (EPI == 0) ? g_xn2 : (EPI == 1) ? g_yh : (EPI == 2) ? g_xn3 : g_hid;
    const __half* Bp = (EPI == 0) ? g_wcat : (EPI == 1) ? g_wout : (EPI == 2) ? g_w1 : g_w2;
    const float* bp = (EPI == 0) ? g_bias256 : bias;

    int tid = threadIdx.x;
    int wid = tid >> 5, lane = tid & 31;
    int g = lane >> 2, t4 = lane & 3;
    int row0 = blockIdx.y * 128, col0 = blockIdx.x * 64;
    int m0 = wid * 32;
    int lrow = lane & 7, lmat = lane >> 3;
    int a_moff = (lmat & 1)*8, a_koff = (lmat >> 1)*8;
    int b_noff = (lmat >> 1)*8, b_koff = (lmat & 1)*8;

    float acc[2][8][4];
    #pragma unroll
    for (int mi = 0; mi < 2; mi++)
        #pragma unroll
        for (int ni = 0; ni < 8; ni++)
            #pragma unroll
            for (int e = 0; e < 4; e++) acc[mi][ni][e] = 0.f;

    const int NK = K / 64;
    auto load_slab = [&](int kt, int st) {
        __half* As = stage0 + st*STAGEH;
        __half* Bs = As + 128*PITCHH;
        int k0 = kt * 64;
        #pragma unroll
        for (int i = 0; i < 8; i++) {
            int idx = tid + 128*i;
            int m = idx >> 3, c = idx & 7;
            cp16(As + m*PITCHH + c*8, A + (size_t)(row0 + m)*K + k0 + c*8);
        }
        #pragma unroll
        for (int i = 0; i < 4; i++) {
            int idx = tid + 128*i;
            int n = idx >> 3, c = idx & 7;
            cp16(Bs + n*PITCHH + c*8, Bp + (size_t)(col0 + n)*K + k0 + c*8);
        }
    };
    load_slab(0, 0);
    cp_commit();
    for (int kt = 0; kt < NK; kt++) {
        int cur = kt & 1;
        if (kt + 1 < NK) { load_slab(kt + 1, (kt + 1) & 1); cp_commit(); cp_wait<1>(); }
        else cp_wait<0>();
        __syncthreads();
        const __half* As = stage0 + cur*STAGEH;
        const __half* Bs = As + 128*PITCHH;
        #pragma unroll
        for (int ks = 0; ks < 4; ks++) {
            int kb = ks*16;
            uint32_t a[2][4], b[4][4];
            #pragma unroll
            for (int mi = 0; mi < 2; mi++)
                ldm4(a[mi], As + (m0 + mi*16 + lrow + a_moff)*PITCHH + kb + a_koff);
            #pragma unroll
            for (int nb = 0; nb < 4; nb++)
                ldm4(b[nb], Bs + (nb*16 + lrow + b_noff)*PITCHH + kb + b_koff);
            #pragma unroll
            for (int mi = 0; mi < 2; mi++)
                #pragma unroll
                for (int ni = 0; ni < 8; ni++)
                    mma_f16(acc[mi][ni], a[mi], &b[ni >> 1][(ni & 1)*2]);
        }
        __syncthreads();
    }

    if (EPI == 0 || EPI == 2) {
        #pragma unroll
        for (int mi = 0; mi < 2; mi++)
            #pragma unroll
            for (int ni = 0; ni < 8; ni++)
                #pragma unroll
                for (int e = 0; e < 4; e++) {
                    int m = row0 + m0 + mi*16 + g + ((e >> 1) << 3);
                    int n = col0 + ni*8 + t4*2 + (e & 1);
                    float v = acc[mi][ni][e] + bp[n];
                    if (EPI == 2) {
                        v = 0.5f * v * (1.f + erff(v * 0.7071067811865476f));
                        g_hid[(size_t)m*N + n] = __float2half(v);
                    } else {
                        g_proj[(size_t)m*N + n] = v;
                    }
                }
    } else {
        float* T = reinterpret_cast<float*>(smc);   // 64 x 128, pitch 129
        __syncthreads();
        #pragma unroll
        for (int mi = 0; mi < 2; mi++)
            #pragma unroll
            for (int ni = 0; ni < 8; ni++)
                #pragma unroll
                for (int e = 0; e < 4; e++) {
                    int ml = m0 + mi*16 + g + ((e >> 1) << 3);
                    int nl = ni*8 + t4*2 + (e & 1);
                    int n = col0 + nl;
                    float v = acc[mi][ni][e] + bp[n];
                    if (EPI == 1) {
                        float d = fminf(fmaxf(Dp[n], -2.f), 2.f);
                        v += d * g_xn1[(size_t)(row0 + ml)*DIM + n];
                    }
                    T[nl*129 + ml] = v;
                }
        __syncthreads();
        int bb = row0 >> 12, hw0 = row0 & (HWSZ-1);
        float aM = (EPI == 3) ? alpha[0] : 0.f;
        #pragma unroll
        for (int i = 0; i < 64; i++) {
            int idx = tid + 128*i;
            int nl = idx >> 7, ml = idx & 127;
            size_t adr = ((size_t)(bb*DIM + col0 + nl))*HWSZ + hw0 + ml;
            if (EPI == 1) g_ssm[adr] = T[nl*129 + ml];
            else          Cout[adr] = g_xr[adr] + aM * T[nl*129 + ml];
        }
    }
}

// smem bytes: mainloop vs transpose epilogue
#define SMEM_MAIN (2*STAGEH*2)          // 55296 B
#define SMEM_TRANS (64*129*4)           // 33024 B
#define SMEM_K (SMEM_MAIN > SMEM_TRANS ? SMEM_MAIN : SMEM_TRANS)

// ---------------- launch ----------------
extern "C" void kernel_launch(void* const* d_in, const int* in_sizes, int n_in,
                              void* d_out, int out_size)
{
    const float* x        = (const float*)d_in[0];
    const float* ln1_g    = (const float*)d_in[1];
    const float* ln1_b    = (const float*)d_in[2];
    const float* ln2_g    = (const float*)d_in[3];
    const float* ln2_b    = (const float*)d_in[4];
    const float* dw_w     = (const float*)d_in[5];
    const float* bn_g     = (const float*)d_in[6];
    const float* bn_b     = (const float*)d_in[7];
    const float* bn_rm    = (const float*)d_in[8];
    const float* bn_rv    = (const float*)d_in[9];
    const float* ssm_ln_g = (const float*)d_in[10];
    const float* ssm_ln_b = (const float*)d_in[11];
    const float* xp_w     = (const float*)d_in[12];
    const float* xp_b     = (const float*)d_in[13];
    const float* dt_w     = (const float*)d_in[14];
    const float* dt_b     = (const float*)d_in[15];
    const float* A_log    = (const float*)d_in[16];
    const float* B_w      = (const float*)d_in[17];
    const float* C_w      = (const float*)d_in[18];
    const float* D_param  = (const float*)d_in[19];
    const float* out_w    = (const float*)d_in[20];
    const float* out_b    = (const float*)d_in[21];
    const float* mlp_w1   = (const float*)d_in[22];
    const float* mlp_b1   = (const float*)d_in[23];
    const float* mlp_w2   = (const float*)d_in[24];
    const float* mlp_b2   = (const float*)d_in[25];
    const float* aL       = (const float*)d_in[26];
    const float* aS       = (const float*)d_in[27];
    const float* aM       = (const float*)d_in[28];
    float* out = (float*)d_out;

    cudaFuncSetAttribute(k_mma<0,256,192>, cudaFuncAttributeMaxDynamicSharedMemorySize, SMEM_K);
    cudaFuncSetAttribute(k_mma<1,192,64>,  cudaFuncAttributeMaxDynamicSharedMemorySize, SMEM_K);
    cudaFuncSetAttribute(k_mma<2,HID,192>, cudaFuncAttributeMaxDynamicSharedMemorySize, SMEM_K);
    cudaFuncSetAttribute(k_mma<3,192,HID>, cudaFuncAttributeMaxDynamicSharedMemorySize, SMEM_K);

    k_prep<<<576, 256>>>(dt_w, B_w, C_w, xp_w, dt_b, xp_b, A_log, out_w, mlp_w1, mlp_w2);
    k_ln<0><<<TOK/32, 1024>>>(x, ln1_g, ln1_b, ssm_ln_g, ssm_ln_b);
    k_mma<0, 256, 192><<<dim3(4, TOK/128), 128, SMEM_K>>>(nullptr, nullptr, nullptr, nullptr);
    k_scan1<<<NB*NCH, ST>>>();
    k_scan2<<<64, 256>>>();
    k_scan3<<<NB*NCH, ST>>>();
    k_mma<1, 192, 64><<<dim3(3, TOK/128), 128, SMEM_K>>>(out_b, D_param, nullptr, nullptr);
    k_combine<<<dim3(16, DIM, NB), 256>>>(x, dw_w, bn_g, bn_b, bn_rm, bn_rv, aL, aS);
    k_ln<1><<<TOK/32, 1024>>>(nullptr, ln2_g, ln2_b, nullptr, nullptr);
    k_mma<2, HID, 192><<<dim3(12, TOK/128), 128, SMEM_K>>>(mlp_b1, nullptr, nullptr, nullptr);
    k_mma<3, 192, HID><<<dim3(3, TOK/128), 128, SMEM_K>>>(mlp_b2, nullptr, aM, out);
}